// round 1
// baseline (speedup 1.0000x reference)
#include <cuda_runtime.h>
#include <math.h>

#define N_TOK 1024
#define DDIM  1024
#define HDIM  1024
#define NEXP  8
#define TOPK  2

#define BM 64
#define BN 64
#define BK 16
#define MAX_ROWS 3648            // 2048 routed + 8*63 pad + 1024 shared, rounded up
#define MAX_TILES (MAX_ROWS/BM)  // 57

// ---------------- device scratch (static, allocation-free) ----------------
__device__ int   g_sel[N_TOK*TOPK];
__device__ float g_wtk[N_TOK*TOPK];
__device__ int   g_cnt[NEXP];
__device__ int   g_fill[NEXP];
__device__ int   g_off[NEXP+2];
__device__ int   g_tile_exp[MAX_TILES];
__device__ int   g_num_tiles;
__device__ int   g_row_tok[MAX_ROWS];
__device__ float g_row_wt[MAX_ROWS];
__device__ float g_act[(size_t)MAX_ROWS*HDIM];   // ~14.9 MB intermediate

// ---------------- 1. router: logits -> softmax -> top2 ----------------
__global__ void router_kernel(const float* __restrict__ x,
                              const float* __restrict__ rw,
                              const float* __restrict__ bias) {
    int warp = threadIdx.x >> 5, lane = threadIdx.x & 31;
    int tok = blockIdx.x * 8 + warp;
    if (tok >= N_TOK) return;
    const float* xr = x + (size_t)tok * DDIM;
    float acc[NEXP];
#pragma unroll
    for (int e = 0; e < NEXP; e++) acc[e] = 0.f;
    for (int d = lane; d < DDIM; d += 32) {
        float xv = xr[d];
        const float* r = rw + (size_t)d * NEXP;
#pragma unroll
        for (int e = 0; e < NEXP; e++) acc[e] += xv * r[e];
    }
#pragma unroll
    for (int e = 0; e < NEXP; e++)
#pragma unroll
        for (int o = 16; o > 0; o >>= 1)
            acc[e] += __shfl_xor_sync(0xffffffffu, acc[e], o);
    if (lane == 0) {
        float m = acc[0];
#pragma unroll
        for (int e = 1; e < NEXP; e++) m = fmaxf(m, acc[e]);
        float sc[NEXP]; float s = 0.f;
#pragma unroll
        for (int e = 0; e < NEXP; e++) { sc[e] = expf(acc[e] - m); s += sc[e]; }
        float inv = 1.f / s;
#pragma unroll
        for (int e = 0; e < NEXP; e++) sc[e] *= inv;
        // top-2 on (score + bias), ties -> lower index (strict >)
        int i0 = 0; float b0 = sc[0] + bias[0];
#pragma unroll
        for (int e = 1; e < NEXP; e++) { float v = sc[e] + bias[e]; if (v > b0) { b0 = v; i0 = e; } }
        int i1 = -1; float b1 = -1e30f;
#pragma unroll
        for (int e = 0; e < NEXP; e++) {
            if (e == i0) continue;
            float v = sc[e] + bias[e]; if (v > b1) { b1 = v; i1 = e; }
        }
        g_sel[tok*2]   = i0;  g_sel[tok*2+1] = i1;
        g_wtk[tok*2]   = sc[i0]; g_wtk[tok*2+1] = sc[i1];
    }
}

// ---------------- 2. build padded per-expert row list ----------------
__global__ void build_kernel() {
    int tid = threadIdx.x;
    for (int i = tid; i < MAX_ROWS; i += blockDim.x) { g_row_tok[i] = -1; g_row_wt[i] = 0.f; }
    if (tid < NEXP) { g_cnt[tid] = 0; g_fill[tid] = 0; }
    __syncthreads();
    for (int i = tid; i < N_TOK*TOPK; i += blockDim.x)
        atomicAdd(&g_cnt[g_sel[i]], 1);
    __syncthreads();
    if (tid == 0) {
        int off = 0;
        for (int e = 0; e < NEXP; e++) {
            g_off[e] = off;
            off += ((g_cnt[e] + BM - 1) / BM) * BM;
        }
        g_off[NEXP] = off;            // shared-expert segment start
        int total = off + N_TOK;      // shared segment is exactly N_TOK (mult of BM)
        g_off[NEXP+1] = total;
        int nt = total / BM;
        g_num_tiles = nt;
        for (int t = 0; t < nt; t++) {
            int row = t * BM;
            int e = 0;
            while (e < NEXP+1 && row >= g_off[e+1]) e++;
            g_tile_exp[t] = e;        // e==NEXP -> shared expert
        }
    }
    __syncthreads();
    for (int i = tid; i < N_TOK*TOPK; i += blockDim.x) {
        int e = g_sel[i];
        int p = g_off[e] + atomicAdd(&g_fill[e], 1);
        g_row_tok[p] = i >> 1;        // token = pair / TOPK
        g_row_wt[p]  = g_wtk[i];
    }
    for (int t = tid; t < N_TOK; t += blockDim.x) {
        int p = g_off[NEXP] + t;
        g_row_tok[p] = t;
        g_row_wt[p]  = 1.0f;
    }
}

// ---------------- 3. GEMM1: act = silu(x@W1) * (x@W3) ----------------
__global__ void __launch_bounds__(256) gemm1_kernel(
        const float* __restrict__ x,
        const float* __restrict__ w1, const float* __restrict__ w3,
        const float* __restrict__ sw1, const float* __restrict__ sw3) {
    int tile = blockIdx.x;
    if (tile >= g_num_tiles) return;
    int e = g_tile_exp[tile];
    const float* W1 = (e < NEXP) ? (w1 + (size_t)e * DDIM * HDIM) : sw1;
    const float* W3 = (e < NEXP) ? (w3 + (size_t)e * DDIM * HDIM) : sw3;
    int base = tile * BM;
    int h0   = blockIdx.y * BN;

    __shared__ float As[BK][BM+4];
    __shared__ float B1[BK][BN];
    __shared__ float B3[BK][BN];
    __shared__ int   toks[BM];

    int tid = threadIdx.x;
    if (tid < BM) toks[tid] = g_row_tok[base + tid];
    __syncthreads();

    int tx = tid & 15, ty = tid >> 4;
    float a1[4][4], a3[4][4];
#pragma unroll
    for (int i = 0; i < 4; i++)
#pragma unroll
        for (int j = 0; j < 4; j++) { a1[i][j] = 0.f; a3[i][j] = 0.f; }

    int lr  = tid >> 2;          // row for x load
    int lk0 = (tid & 3) * 4;     // k offset for x load

    for (int k0 = 0; k0 < DDIM; k0 += BK) {
        {
            int tok = toks[lr];
            float v0 = 0.f, v1 = 0.f, v2 = 0.f, v3 = 0.f;
            if (tok >= 0) {
                const float* p = x + (size_t)tok * DDIM + k0 + lk0;
                v0 = p[0]; v1 = p[1]; v2 = p[2]; v3 = p[3];
            }
            As[lk0  ][lr] = v0; As[lk0+1][lr] = v1;
            As[lk0+2][lr] = v2; As[lk0+3][lr] = v3;
        }
#pragma unroll
        for (int j = 0; j < 4; j++) {
            int l = tid + 256*j;
            int c = l & 63, kk = l >> 6;
            B1[kk][c] = W1[(size_t)(k0+kk) * HDIM + h0 + c];
            B3[kk][c] = W3[(size_t)(k0+kk) * HDIM + h0 + c];
        }
        __syncthreads();
#pragma unroll
        for (int kk = 0; kk < BK; kk++) {
            float av[4], b1v[4], b3v[4];
#pragma unroll
            for (int i = 0; i < 4; i++) av[i] = As[kk][ty*4+i];
#pragma unroll
            for (int j = 0; j < 4; j++) { b1v[j] = B1[kk][tx*4+j]; b3v[j] = B3[kk][tx*4+j]; }
#pragma unroll
            for (int i = 0; i < 4; i++)
#pragma unroll
                for (int j = 0; j < 4; j++) {
                    a1[i][j] += av[i] * b1v[j];
                    a3[i][j] += av[i] * b3v[j];
                }
        }
        __syncthreads();
    }
#pragma unroll
    for (int i = 0; i < 4; i++) {
        size_t rowoff = (size_t)(base + ty*4 + i) * HDIM + h0 + tx*4;
#pragma unroll
        for (int j = 0; j < 4; j++) {
            float h1 = a1[i][j], h3 = a3[i][j];
            float act = (h1 / (1.f + expf(-h1))) * h3;   // silu(h1)*h3
            g_act[rowoff + j] = act;
        }
    }
}

// ---------------- 4. GEMM2: y = act @ W2 ; out[token] += wt * y ----------------
__global__ void __launch_bounds__(256) gemm2_kernel(
        const float* __restrict__ w2, const float* __restrict__ sw2,
        float* __restrict__ out) {
    int tile = blockIdx.x;
    if (tile >= g_num_tiles) return;
    int e = g_tile_exp[tile];
    const float* W2 = (e < NEXP) ? (w2 + (size_t)e * HDIM * DDIM) : sw2;
    int base = tile * BM;
    int d0   = blockIdx.y * BN;

    __shared__ float As[BK][BM+4];
    __shared__ float Bs[BK][BN];
    __shared__ int   toks[BM];
    __shared__ float wts[BM];

    int tid = threadIdx.x;
    if (tid < BM) { toks[tid] = g_row_tok[base + tid]; wts[tid] = g_row_wt[base + tid]; }
    __syncthreads();

    int tx = tid & 15, ty = tid >> 4;
    float acc[4][4];
#pragma unroll
    for (int i = 0; i < 4; i++)
#pragma unroll
        for (int j = 0; j < 4; j++) acc[i][j] = 0.f;

    int lr  = tid >> 2;
    int lk0 = (tid & 3) * 4;

    for (int k0 = 0; k0 < HDIM; k0 += BK) {
        {
            const float* p = g_act + (size_t)(base + lr) * HDIM + k0 + lk0;
            As[lk0  ][lr] = p[0]; As[lk0+1][lr] = p[1];
            As[lk0+2][lr] = p[2]; As[lk0+3][lr] = p[3];
        }
#pragma unroll
        for (int j = 0; j < 4; j++) {
            int l = tid + 256*j;
            int c = l & 63, kk = l >> 6;
            Bs[kk][c] = W2[(size_t)(k0+kk) * DDIM + d0 + c];
        }
        __syncthreads();
#pragma unroll
        for (int kk = 0; kk < BK; kk++) {
            float av[4], bv[4];
#pragma unroll
            for (int i = 0; i < 4; i++) av[i] = As[kk][ty*4+i];
#pragma unroll
            for (int j = 0; j < 4; j++) bv[j] = Bs[kk][tx*4+j];
#pragma unroll
            for (int i = 0; i < 4; i++)
#pragma unroll
                for (int j = 0; j < 4; j++) acc[i][j] += av[i] * bv[j];
        }
        __syncthreads();
    }
#pragma unroll
    for (int i = 0; i < 4; i++) {
        int r = ty*4 + i;
        int tok = toks[r];
        if (tok < 0) continue;
        float wt = wts[r];
        float* op = out + (size_t)tok * DDIM + d0 + tx*4;
#pragma unroll
        for (int j = 0; j < 4; j++)
            atomicAdd(&op[j], wt * acc[i][j]);
    }
}

// ---------------- launch ----------------
extern "C" void kernel_launch(void* const* d_in, const int* in_sizes, int n_in,
                              void* d_out, int out_size) {
    const float* x    = (const float*)d_in[0];
    const float* rw   = (const float*)d_in[1];
    const float* bias = (const float*)d_in[2];
    const float* w1   = (const float*)d_in[3];
    const float* w2   = (const float*)d_in[4];
    const float* w3   = (const float*)d_in[5];
    const float* sw1  = (const float*)d_in[6];
    const float* sw2  = (const float*)d_in[7];
    const float* sw3  = (const float*)d_in[8];
    float* out = (float*)d_out;

    cudaMemsetAsync(out, 0, (size_t)out_size * sizeof(float));

    router_kernel<<<N_TOK/8, 256>>>(x, rw, bias);
    build_kernel<<<1, 256>>>();

    dim3 g1(MAX_TILES, HDIM / BN);
    gemm1_kernel<<<g1, 256>>>(x, w1, w3, sw1, sw3);

    dim3 g2(MAX_TILES, DDIM / BN);
    gemm2_kernel<<<g2, 256>>>(w2, sw2, out);
}

// round 4
// speedup vs baseline: 2.0363x; 2.0363x over previous
#include <cuda_runtime.h>
#include <cuda_bf16.h>
#include <math.h>
#include <stdint.h>

#define N_TOK 1024
#define DDIM  1024
#define HDIM  1024
#define NEXP  8
#define TOPK  2
#define BM    128
#define BN    64
#define BK    32
#define MAX_ROWS  4096
#define MAX_TILES 32

// ---------------- device scratch ----------------
__device__ __nv_bfloat16 g_w1t_h[9ull*1024*1024];
__device__ __nv_bfloat16 g_w1t_l[9ull*1024*1024];
__device__ __nv_bfloat16 g_w3t_h[9ull*1024*1024];
__device__ __nv_bfloat16 g_w3t_l[9ull*1024*1024];
__device__ __nv_bfloat16 g_w2t_h[9ull*1024*1024];
__device__ __nv_bfloat16 g_w2t_l[9ull*1024*1024];
__device__ __nv_bfloat16 g_xh[1024*1024];
__device__ __nv_bfloat16 g_xl[1024*1024];
__device__ __nv_bfloat16 g_acth[(size_t)MAX_ROWS*HDIM];
__device__ __nv_bfloat16 g_actl[(size_t)MAX_ROWS*HDIM];

__device__ int   g_sel[N_TOK*TOPK];
__device__ float g_wtk[N_TOK*TOPK];
__device__ int   g_cnt[NEXP];
__device__ int   g_fill[NEXP];
__device__ int   g_off[NEXP+2];
__device__ int   g_tile_exp[MAX_TILES];
__device__ int   g_num_tiles;
__device__ int   g_row_tok[MAX_ROWS];
__device__ float g_row_wt[MAX_ROWS];

// ---------------- helpers ----------------
__device__ __forceinline__ uint32_t smem_u32(const void* p) {
    uint32_t a;
    asm("{ .reg .u64 t; cvta.to.shared.u64 t, %1; cvt.u32.u64 %0, t; }" : "=r"(a) : "l"(p));
    return a;
}
__device__ __forceinline__ void cp16(uint32_t dst, const void* src, int sz) {
    asm volatile("cp.async.cg.shared.global [%0], [%1], 16, %2;"
                 :: "r"(dst), "l"(src), "r"(sz) : "memory");
}
#define CP_COMMIT() asm volatile("cp.async.commit_group;" ::: "memory")
#define CP_WAIT(n)  asm volatile("cp.async.wait_group %0;" :: "n"(n) : "memory")

__device__ __forceinline__ void ldm4(uint32_t* r, uint32_t addr) {
    asm volatile("ldmatrix.sync.aligned.m8n8.x4.shared.b16 {%0,%1,%2,%3}, [%4];"
                 : "=r"(r[0]), "=r"(r[1]), "=r"(r[2]), "=r"(r[3]) : "r"(addr));
}
__device__ __forceinline__ void ldm2(uint32_t* r, uint32_t addr) {
    asm volatile("ldmatrix.sync.aligned.m8n8.x2.shared.b16 {%0,%1}, [%2];"
                 : "=r"(r[0]), "=r"(r[1]) : "r"(addr));
}
__device__ __forceinline__ void mma_bf16(float* d, const uint32_t* a, const uint32_t* b) {
    asm volatile(
        "mma.sync.aligned.m16n8k16.row.col.f32.bf16.bf16.f32 "
        "{%0,%1,%2,%3},{%4,%5,%6,%7},{%8,%9},{%0,%1,%2,%3};"
        : "+f"(d[0]), "+f"(d[1]), "+f"(d[2]), "+f"(d[3])
        : "r"(a[0]), "r"(a[1]), "r"(a[2]), "r"(a[3]), "r"(b[0]), "r"(b[1]));
}
__device__ __forceinline__ uint32_t pack2(float a, float b) {
    __nv_bfloat16 ha = __float2bfloat16_rn(a), hb = __float2bfloat16_rn(b);
    return (uint32_t)__bfloat16_as_ushort(ha) | ((uint32_t)__bfloat16_as_ushort(hb) << 16);
}
__device__ __forceinline__ uint32_t pack2lo(float a, float b) {
    __nv_bfloat16 ha = __float2bfloat16_rn(a), hb = __float2bfloat16_rn(b);
    float ra = a - __bfloat162float(ha), rb = b - __bfloat162float(hb);
    return pack2(ra, rb);
}

// ---------------- 1. router ----------------
__global__ void router_kernel(const float* __restrict__ x,
                              const float* __restrict__ rw,
                              const float* __restrict__ bias) {
    int warp = threadIdx.x >> 5, lane = threadIdx.x & 31;
    int tok = blockIdx.x * 8 + warp;
    if (tok >= N_TOK) return;
    const float* xr = x + (size_t)tok * DDIM;
    float acc[NEXP];
#pragma unroll
    for (int e = 0; e < NEXP; e++) acc[e] = 0.f;
    for (int d = lane; d < DDIM; d += 32) {
        float xv = xr[d];
        const float* r = rw + (size_t)d * NEXP;
#pragma unroll
        for (int e = 0; e < NEXP; e++) acc[e] += xv * r[e];
    }
#pragma unroll
    for (int e = 0; e < NEXP; e++)
#pragma unroll
        for (int o = 16; o > 0; o >>= 1)
            acc[e] += __shfl_xor_sync(0xffffffffu, acc[e], o);
    if (lane == 0) {
        float m = acc[0];
#pragma unroll
        for (int e = 1; e < NEXP; e++) m = fmaxf(m, acc[e]);
        float sc[NEXP]; float s = 0.f;
#pragma unroll
        for (int e = 0; e < NEXP; e++) { sc[e] = expf(acc[e] - m); s += sc[e]; }
        float inv = 1.f / s;
#pragma unroll
        for (int e = 0; e < NEXP; e++) sc[e] *= inv;
        int i0 = 0; float b0 = sc[0] + bias[0];
#pragma unroll
        for (int e = 1; e < NEXP; e++) { float v = sc[e] + bias[e]; if (v > b0) { b0 = v; i0 = e; } }
        int i1 = -1; float b1 = -1e30f;
#pragma unroll
        for (int e = 0; e < NEXP; e++) {
            if (e == i0) continue;
            float v = sc[e] + bias[e]; if (v > b1) { b1 = v; i1 = e; }
        }
        g_sel[tok*2]   = i0;  g_sel[tok*2+1] = i1;
        g_wtk[tok*2]   = sc[i0]; g_wtk[tok*2+1] = sc[i1];
    }
}

// ---------------- 2. build padded row list ----------------
__global__ void build_kernel() {
    int tid = threadIdx.x;
    for (int i = tid; i < MAX_ROWS; i += blockDim.x) { g_row_tok[i] = -1; g_row_wt[i] = 0.f; }
    if (tid < NEXP) { g_cnt[tid] = 0; g_fill[tid] = 0; }
    __syncthreads();
    for (int i = tid; i < N_TOK*TOPK; i += blockDim.x)
        atomicAdd(&g_cnt[g_sel[i]], 1);
    __syncthreads();
    if (tid == 0) {
        int off = 0;
        for (int e = 0; e < NEXP; e++) {
            g_off[e] = off;
            off += ((g_cnt[e] + BM - 1) / BM) * BM;
        }
        g_off[NEXP] = off;
        int total = off + N_TOK;
        g_off[NEXP+1] = total;
        int nt = total / BM;
        g_num_tiles = nt;
        for (int t = 0; t < nt; t++) {
            int row = t * BM;
            int e = 0;
            while (e < NEXP+1 && row >= g_off[e+1]) e++;
            g_tile_exp[t] = e;   // e==8 -> shared-expert slot
        }
    }
    __syncthreads();
    for (int i = tid; i < N_TOK*TOPK; i += blockDim.x) {
        int e = g_sel[i];
        int p = g_off[e] + atomicAdd(&g_fill[e], 1);
        g_row_tok[p] = i >> 1;
        g_row_wt[p]  = g_wtk[i];
    }
    for (int t = tid; t < N_TOK; t += blockDim.x) {
        int p = g_off[NEXP] + t;
        g_row_tok[p] = t;
        g_row_wt[p]  = 1.0f;
    }
}

// ---------------- 3. convert+transpose weights -> bf16 hi/lo [slot][N][K] ----------------
__global__ void convert_weights(const float* __restrict__ w1, const float* __restrict__ w2,
                                const float* __restrict__ w3,
                                const float* __restrict__ sw1, const float* __restrict__ sw2,
                                const float* __restrict__ sw3) {
    __shared__ float t[32][33];
    int e = blockIdx.y;                 // 0..8 (8 = shared)
    int mat = blockIdx.z;               // 0=w1, 1=w3, 2=w2
    int tile_r = (blockIdx.x >> 5) << 5;
    int tile_c = (blockIdx.x & 31) << 5;
    const float* src;
    __nv_bfloat16 *dh, *dl;
    size_t eo = (size_t)e << 20;
    if (mat == 0)      { src = (e < 8) ? w1 + eo : sw1; dh = g_w1t_h + eo; dl = g_w1t_l + eo; }
    else if (mat == 1) { src = (e < 8) ? w3 + eo : sw3; dh = g_w3t_h + eo; dl = g_w3t_l + eo; }
    else               { src = (e < 8) ? w2 + eo : sw2; dh = g_w2t_h + eo; dl = g_w2t_l + eo; }

    int tx = threadIdx.x, ty = threadIdx.y;
#pragma unroll
    for (int j = 0; j < 4; j++)
        t[ty + 8*j][tx] = src[(size_t)(tile_r + ty + 8*j) * 1024 + tile_c + tx];
    __syncthreads();
    bool lohalf = tx >= 16;
    int l = tx & 15;
#pragma unroll
    for (int j = 0; j < 4; j++) {
        int cy = ty + 8*j;
        float v0 = t[2*l][cy], v1 = t[2*l+1][cy];
        uint32_t packed = lohalf ? pack2lo(v0, v1) : pack2(v0, v1);
        __nv_bfloat16* base = lohalf ? dl : dh;
        uint32_t* dst = (uint32_t*)(base + (size_t)(tile_c + cy) * 1024 + tile_r) + l;
        *dst = packed;
    }
}

// ---------------- 4. convert x -> bf16 hi/lo ----------------
__global__ void convert_x(const float* __restrict__ x) {
    int i = (blockIdx.x * 256 + threadIdx.x) * 8;
    float4 a = *(const float4*)(x + i);
    float4 b = *(const float4*)(x + i + 4);
    uint4 h = make_uint4(pack2(a.x, a.y), pack2(a.z, a.w), pack2(b.x, b.y), pack2(b.z, b.w));
    uint4 lo = make_uint4(pack2lo(a.x, a.y), pack2lo(a.z, a.w), pack2lo(b.x, b.y), pack2lo(b.z, b.w));
    *(uint4*)(g_xh + i) = h;
    *(uint4*)(g_xl + i) = lo;
}

// ---------------- GEMM smem layout constants (bytes) ----------------
// stride per row: 40 bf16 = 80 bytes (conflict-free for ldmatrix)
#define RS 40
// gemm1 stage: Ah(128x40) Al B1h(64x40) B1l B3h B3l
#define G1_AH  0
#define G1_AL  10240
#define G1_B1H 20480
#define G1_B1L 25600
#define G1_B3H 30720
#define G1_B3L 35840
#define G1_STG 40960
// gemm2 stage: Ah Al Bh Bl
#define G2_AH  0
#define G2_AL  10240
#define G2_BH  20480
#define G2_BL  25600
#define G2_STG 30720

// ---------------- 5. GEMM1: act = silu(x@W1) * (x@W3) ----------------
__global__ void __launch_bounds__(256) gemm1_kernel() {
    extern __shared__ __align__(16) char dyn[];
    __shared__ int toks_sh[BM];

    int tile = blockIdx.x;
    if (tile >= g_num_tiles) return;
    int e  = g_tile_exp[tile];
    int h0 = blockIdx.y * BN;
    int tid = threadIdx.x, lane = tid & 31, wid = tid >> 5;
    int wm = wid & 1, wn = wid >> 1;      // warp tile: 64(m) x 16(n)

    if (tid < BM) toks_sh[tid] = g_row_tok[tile * BM + tid];
    __syncthreads();

    const __nv_bfloat16* b1h = g_w1t_h + ((size_t)e << 20);
    const __nv_bfloat16* b1l = g_w1t_l + ((size_t)e << 20);
    const __nv_bfloat16* b3h = g_w3t_h + ((size_t)e << 20);
    const __nv_bfloat16* b3l = g_w3t_l + ((size_t)e << 20);
    uint32_t smem = smem_u32(dyn);

    // per-thread fill coords
    int ar0 = (tid*2) >> 2,  ak0 = ((tid*2) & 3) * 8;
    int ar1 = (tid*2+1) >> 2, ak1 = ((tid*2+1) & 3) * 8;
    int br = tid >> 2,       bk = (tid & 3) * 8;
    int atok0 = toks_sh[ar0], atok1 = toks_sh[ar1];
    size_t axo0 = ((size_t)(atok0 < 0 ? 0 : atok0) << 10) + ak0;
    size_t axo1 = ((size_t)(atok1 < 0 ? 0 : atok1) << 10) + ak1;
    int asz0 = atok0 < 0 ? 0 : 16, asz1 = atok1 < 0 ? 0 : 16;
    size_t bro = ((size_t)(h0 + br) << 10) + bk;
    uint32_t adst0 = (uint32_t)(ar0*RS + ak0) * 2;
    uint32_t adst1 = (uint32_t)(ar1*RS + ak1) * 2;
    uint32_t bdst  = (uint32_t)(br*RS + bk) * 2;

#define G1_FILL(k0, sb) do { \
    cp16((sb) + G1_AH + adst0, g_xh + axo0 + (k0), asz0); \
    cp16((sb) + G1_AH + adst1, g_xh + axo1 + (k0), asz1); \
    cp16((sb) + G1_AL + adst0, g_xl + axo0 + (k0), asz0); \
    cp16((sb) + G1_AL + adst1, g_xl + axo1 + (k0), asz1); \
    cp16((sb) + G1_B1H + bdst, b1h + bro + (k0), 16); \
    cp16((sb) + G1_B1L + bdst, b1l + bro + (k0), 16); \
    cp16((sb) + G1_B3H + bdst, b3h + bro + (k0), 16); \
    cp16((sb) + G1_B3L + bdst, b3l + bro + (k0), 16); \
} while (0)

    float acc1[4][2][4], acc3[4][2][4];
#pragma unroll
    for (int i = 0; i < 4; i++)
#pragma unroll
        for (int j = 0; j < 2; j++)
#pragma unroll
            for (int k = 0; k < 4; k++) { acc1[i][j][k] = 0.f; acc3[i][j][k] = 0.f; }

    int lr = lane & 15, lc8 = (lane >> 4) * 8;
    int bbr = lane & 7, bc8 = ((lane >> 3) & 1) * 8;

    G1_FILL(0, smem);
    CP_COMMIT();

    const int NST = DDIM / BK;   // 32
    for (int s = 0; s < NST; s++) {
        if (s + 1 < NST) {
            uint32_t sb = smem + ((s + 1) & 1) * G1_STG;
            G1_FILL((s + 1) * BK, sb);
            CP_COMMIT();
            CP_WAIT(1);
        } else {
            CP_WAIT(0);
        }
        __syncthreads();
        uint32_t sb = smem + (s & 1) * G1_STG;
#pragma unroll
        for (int ks = 0; ks < 2; ks++) {
            uint32_t ah[4][4], al[4][4];
#pragma unroll
            for (int mf = 0; mf < 4; mf++) {
                uint32_t o = (uint32_t)((wm*64 + mf*16 + lr)*RS + ks*16 + lc8) * 2;
                ldm4(ah[mf], sb + G1_AH + o);
                ldm4(al[mf], sb + G1_AL + o);
            }
            uint32_t f1h[2][2], f1l[2][2], f3h[2][2], f3l[2][2];
#pragma unroll
            for (int nf = 0; nf < 2; nf++) {
                uint32_t o = (uint32_t)((wn*16 + nf*8 + bbr)*RS + ks*16 + bc8) * 2;
                ldm2(f1h[nf], sb + G1_B1H + o);
                ldm2(f1l[nf], sb + G1_B1L + o);
                ldm2(f3h[nf], sb + G1_B3H + o);
                ldm2(f3l[nf], sb + G1_B3L + o);
            }
#pragma unroll
            for (int mf = 0; mf < 4; mf++)
#pragma unroll
                for (int nf = 0; nf < 2; nf++) {
                    mma_bf16(acc1[mf][nf], ah[mf], f1h[nf]);
                    mma_bf16(acc1[mf][nf], al[mf], f1h[nf]);
                    mma_bf16(acc1[mf][nf], ah[mf], f1l[nf]);
                    mma_bf16(acc3[mf][nf], ah[mf], f3h[nf]);
                    mma_bf16(acc3[mf][nf], al[mf], f3h[nf]);
                    mma_bf16(acc3[mf][nf], ah[mf], f3l[nf]);
                }
        }
        __syncthreads();
    }

    // epilogue: silu(d1)*d3 -> bf16 hi/lo
#pragma unroll
    for (int mf = 0; mf < 4; mf++)
#pragma unroll
        for (int nf = 0; nf < 2; nf++) {
            int m = wm*64 + mf*16 + (lane >> 2);
            int h = h0 + wn*16 + nf*8 + (lane & 3)*2;
            float* c1 = acc1[mf][nf];
            float* c3 = acc3[mf][nf];
#pragma unroll
            for (int half = 0; half < 2; half++) {
                float v1a = c1[half*2], v1b = c1[half*2+1];
                float v3a = c3[half*2], v3b = c3[half*2+1];
                float a0 = (v1a / (1.f + expf(-v1a))) * v3a;
                float a1 = (v1b / (1.f + expf(-v1b))) * v3b;
                size_t row = (size_t)(tile*BM + m + half*8);
                size_t off = (row << 10) + h;
                *(uint32_t*)(g_acth + off) = pack2(a0, a1);
                *(uint32_t*)(g_actl + off) = pack2lo(a0, a1);
            }
        }
}

// ---------------- 6. GEMM2: out[tok] += wt * (act @ W2) ----------------
__global__ void __launch_bounds__(256) gemm2_kernel(float* __restrict__ out) {
    extern __shared__ __align__(16) char dyn[];
    __shared__ int   toks_sh[BM];
    __shared__ float wts_sh[BM];

    int tile = blockIdx.x;
    if (tile >= g_num_tiles) return;
    int e  = g_tile_exp[tile];
    int d0 = blockIdx.y * BN;
    int tid = threadIdx.x, lane = tid & 31, wid = tid >> 5;
    int wm = wid & 1, wn = wid >> 1;

    if (tid < BM) {
        toks_sh[tid] = g_row_tok[tile * BM + tid];
        wts_sh[tid]  = g_row_wt[tile * BM + tid];
    }
    __syncthreads();

    const __nv_bfloat16* bh = g_w2t_h + ((size_t)e << 20);
    const __nv_bfloat16* bl = g_w2t_l + ((size_t)e << 20);
    uint32_t smem = smem_u32(dyn);

    int ar0 = (tid*2) >> 2,  ak0 = ((tid*2) & 3) * 8;
    int ar1 = (tid*2+1) >> 2, ak1 = ((tid*2+1) & 3) * 8;
    int br = tid >> 2,       bk = (tid & 3) * 8;
    size_t axo0 = (((size_t)(tile*BM + ar0)) << 10) + ak0;
    size_t axo1 = (((size_t)(tile*BM + ar1)) << 10) + ak1;
    size_t bro  = ((size_t)(d0 + br) << 10) + bk;
    uint32_t adst0 = (uint32_t)(ar0*RS + ak0) * 2;
    uint32_t adst1 = (uint32_t)(ar1*RS + ak1) * 2;
    uint32_t bdst  = (uint32_t)(br*RS + bk) * 2;

#define G2_FILL(k0, sb) do { \
    cp16((sb) + G2_AH + adst0, g_acth + axo0 + (k0), 16); \
    cp16((sb) + G2_AH + adst1, g_acth + axo1 + (k0), 16); \
    cp16((sb) + G2_AL + adst0, g_actl + axo0 + (k0), 16); \
    cp16((sb) + G2_AL + adst1, g_actl + axo1 + (k0), 16); \
    cp16((sb) + G2_BH + bdst, bh + bro + (k0), 16); \
    cp16((sb) + G2_BL + bdst, bl + bro + (k0), 16); \
} while (0)

    float acc[4][2][4];
#pragma unroll
    for (int i = 0; i < 4; i++)
#pragma unroll
        for (int j = 0; j < 2; j++)
#pragma unroll
            for (int k = 0; k < 4; k++) acc[i][j][k] = 0.f;

    int lr = lane & 15, lc8 = (lane >> 4) * 8;
    int bbr = lane & 7, bc8 = ((lane >> 3) & 1) * 8;

    G2_FILL(0, smem);
    CP_COMMIT();

    const int NST = HDIM / BK;
    for (int s = 0; s < NST; s++) {
        if (s + 1 < NST) {
            uint32_t sb = smem + ((s + 1) & 1) * G2_STG;
            G2_FILL((s + 1) * BK, sb);
            CP_COMMIT();
            CP_WAIT(1);
        } else {
            CP_WAIT(0);
        }
        __syncthreads();
        uint32_t sb = smem + (s & 1) * G2_STG;
#pragma unroll
        for (int ks = 0; ks < 2; ks++) {
            uint32_t ah[4][4], al[4][4];
#pragma unroll
            for (int mf = 0; mf < 4; mf++) {
                uint32_t o = (uint32_t)((wm*64 + mf*16 + lr)*RS + ks*16 + lc8) * 2;
                ldm4(ah[mf], sb + G2_AH + o);
                ldm4(al[mf], sb + G2_AL + o);
            }
            uint32_t fh[2][2], fl[2][2];
#pragma unroll
            for (int nf = 0; nf < 2; nf++) {
                uint32_t o = (uint32_t)((wn*16 + nf*8 + bbr)*RS + ks*16 + bc8) * 2;
                ldm2(fh[nf], sb + G2_BH + o);
                ldm2(fl[nf], sb + G2_BL + o);
            }
#pragma unroll
            for (int mf = 0; mf < 4; mf++)
#pragma unroll
                for (int nf = 0; nf < 2; nf++) {
                    mma_bf16(acc[mf][nf], ah[mf], fh[nf]);
                    mma_bf16(acc[mf][nf], al[mf], fh[nf]);
                    mma_bf16(acc[mf][nf], ah[mf], fl[nf]);
                }
        }
        __syncthreads();
    }

#pragma unroll
    for (int mf = 0; mf < 4; mf++)
#pragma unroll
        for (int nf = 0; nf < 2; nf++) {
            int m = wm*64 + mf*16 + (lane >> 2);
            int d = d0 + wn*16 + nf*8 + (lane & 3)*2;
            float* c = acc[mf][nf];
#pragma unroll
            for (int half = 0; half < 2; half++) {
                int mr = m + half*8;
                int tok = toks_sh[mr];
                if (tok < 0) continue;
                float wt = wts_sh[mr];
                float* op = out + ((size_t)tok << 10) + d;
                atomicAdd(op,     wt * c[half*2]);
                atomicAdd(op + 1, wt * c[half*2+1]);
            }
        }
}

// ---------------- launch ----------------
extern "C" void kernel_launch(void* const* d_in, const int* in_sizes, int n_in,
                              void* d_out, int out_size) {
    const float* x    = (const float*)d_in[0];
    const float* rw   = (const float*)d_in[1];
    const float* bias = (const float*)d_in[2];
    const float* w1   = (const float*)d_in[3];
    const float* w2   = (const float*)d_in[4];
    const float* w3   = (const float*)d_in[5];
    const float* sw1  = (const float*)d_in[6];
    const float* sw2  = (const float*)d_in[7];
    const float* sw3  = (const float*)d_in[8];
    float* out = (float*)d_out;

    cudaFuncSetAttribute(gemm1_kernel, cudaFuncAttributeMaxDynamicSharedMemorySize, 2*G1_STG);
    cudaFuncSetAttribute(gemm2_kernel, cudaFuncAttributeMaxDynamicSharedMemorySize, 2*G2_STG);

    cudaMemsetAsync(out, 0, (size_t)out_size * sizeof(float));

    dim3 cb(32, 8);
    convert_weights<<<dim3(1024, 9, 3), cb>>>(w1, w2, w3, sw1, sw2, sw3);
    convert_x<<<512, 256>>>(x);
    router_kernel<<<N_TOK/8, 256>>>(x, rw, bias);
    build_kernel<<<1, 256>>>();

    gemm1_kernel<<<dim3(MAX_TILES, HDIM/BN), 256, 2*G1_STG>>>();
    gemm2_kernel<<<dim3(MAX_TILES, DDIM/BN), 256, 2*G2_STG>>>(out);
}

// round 5
// speedup vs baseline: 2.6742x; 1.3132x over previous
#include <cuda_runtime.h>
#include <cuda_fp16.h>
#include <math.h>
#include <stdint.h>

#define N_TOK 1024
#define DDIM  1024
#define HDIM  1024
#define NEXP  8
#define TOPK  2
#define BM    128
#define BN    64
#define BK    32
#define MAX_ROWS  4096
#define MAX_TILES 32

// ---------------- device scratch ----------------
__device__ __half g_w1t[9ull*1024*1024];   // fp16 weights, transposed [slot][N][K]
__device__ __half g_w3t[9ull*1024*1024];
__device__ __half g_w2t[9ull*1024*1024];
__device__ __half g_xh[1024*1024];         // x hi/lo fp16 pair (22-bit x)
__device__ __half g_xl[1024*1024];
__device__ __half g_acth[(size_t)MAX_ROWS*HDIM];
__device__ __half g_actl[(size_t)MAX_ROWS*HDIM];

__device__ int   g_sel[N_TOK*TOPK];
__device__ float g_wtk[N_TOK*TOPK];
__device__ int   g_tile_exp[MAX_TILES];
__device__ int   g_num_tiles;
__device__ int   g_row_tok[MAX_ROWS];
__device__ float g_row_wt[MAX_ROWS];

// ---------------- helpers ----------------
__device__ __forceinline__ uint32_t smem_u32(const void* p) {
    uint32_t a;
    asm("{ .reg .u64 t; cvta.to.shared.u64 t, %1; cvt.u32.u64 %0, t; }" : "=r"(a) : "l"(p));
    return a;
}
__device__ __forceinline__ void cp16(uint32_t dst, const void* src, int sz) {
    asm volatile("cp.async.cg.shared.global [%0], [%1], 16, %2;"
                 :: "r"(dst), "l"(src), "r"(sz) : "memory");
}
#define CP_COMMIT() asm volatile("cp.async.commit_group;" ::: "memory")
#define CP_WAIT(n)  asm volatile("cp.async.wait_group %0;" :: "n"(n) : "memory")

__device__ __forceinline__ void ldm4(uint32_t* r, uint32_t addr) {
    asm volatile("ldmatrix.sync.aligned.m8n8.x4.shared.b16 {%0,%1,%2,%3}, [%4];"
                 : "=r"(r[0]), "=r"(r[1]), "=r"(r[2]), "=r"(r[3]) : "r"(addr));
}
__device__ __forceinline__ void ldm2(uint32_t* r, uint32_t addr) {
    asm volatile("ldmatrix.sync.aligned.m8n8.x2.shared.b16 {%0,%1}, [%2];"
                 : "=r"(r[0]), "=r"(r[1]) : "r"(addr));
}
__device__ __forceinline__ void mma_f16(float* d, const uint32_t* a, const uint32_t* b) {
    asm volatile(
        "mma.sync.aligned.m16n8k16.row.col.f32.f16.f16.f32 "
        "{%0,%1,%2,%3},{%4,%5,%6,%7},{%8,%9},{%0,%1,%2,%3};"
        : "+f"(d[0]), "+f"(d[1]), "+f"(d[2]), "+f"(d[3])
        : "r"(a[0]), "r"(a[1]), "r"(a[2]), "r"(a[3]), "r"(b[0]), "r"(b[1]));
}
__device__ __forceinline__ uint32_t pack2h(float a, float b) {
    __half ha = __float2half_rn(a), hb = __float2half_rn(b);
    return (uint32_t)__half_as_ushort(ha) | ((uint32_t)__half_as_ushort(hb) << 16);
}
__device__ __forceinline__ uint32_t pack2hlo(float a, float b) {
    __half ha = __float2half_rn(a), hb = __float2half_rn(b);
    float ra = a - __half2float(ha), rb = b - __half2float(hb);
    return pack2h(ra, rb);
}

// ---------------- 1. router ----------------
__global__ void router_kernel(const float* __restrict__ x,
                              const float* __restrict__ rw,
                              const float* __restrict__ bias) {
    int warp = threadIdx.x >> 5, lane = threadIdx.x & 31;
    int tok = blockIdx.x * 8 + warp;
    if (tok >= N_TOK) return;
    const float* xr = x + (size_t)tok * DDIM;
    float acc[NEXP];
#pragma unroll
    for (int e = 0; e < NEXP; e++) acc[e] = 0.f;
    for (int d = lane; d < DDIM; d += 32) {
        float xv = xr[d];
        const float* r = rw + (size_t)d * NEXP;
#pragma unroll
        for (int e = 0; e < NEXP; e++) acc[e] += xv * r[e];
    }
#pragma unroll
    for (int e = 0; e < NEXP; e++)
#pragma unroll
        for (int o = 16; o > 0; o >>= 1)
            acc[e] += __shfl_xor_sync(0xffffffffu, acc[e], o);
    if (lane == 0) {
        float m = acc[0];
#pragma unroll
        for (int e = 1; e < NEXP; e++) m = fmaxf(m, acc[e]);
        float sc[NEXP]; float s = 0.f;
#pragma unroll
        for (int e = 0; e < NEXP; e++) { sc[e] = expf(acc[e] - m); s += sc[e]; }
        float inv = 1.f / s;
#pragma unroll
        for (int e = 0; e < NEXP; e++) sc[e] *= inv;
        int i0 = 0; float b0 = sc[0] + bias[0];
#pragma unroll
        for (int e = 1; e < NEXP; e++) { float v = sc[e] + bias[e]; if (v > b0) { b0 = v; i0 = e; } }
        int i1 = -1; float b1 = -1e30f;
#pragma unroll
        for (int e = 0; e < NEXP; e++) {
            if (e == i0) continue;
            float v = sc[e] + bias[e]; if (v > b1) { b1 = v; i1 = e; }
        }
        g_sel[tok*2]   = i0;  g_sel[tok*2+1] = i1;
        g_wtk[tok*2]   = sc[i0]; g_wtk[tok*2+1] = sc[i1];
    }
}

// ---------------- 2. build padded row list (smem counters) ----------------
__global__ void build_kernel() {
    __shared__ int cnt[NEXP], off[NEXP+2], fill[NEXP];
    int tid = threadIdx.x;
    for (int i = tid; i < MAX_ROWS; i += 256) { g_row_tok[i] = -1; g_row_wt[i] = 0.f; }
    if (tid < NEXP) { cnt[tid] = 0; fill[tid] = 0; }
    __syncthreads();
    for (int i = tid; i < N_TOK*TOPK; i += 256)
        atomicAdd(&cnt[g_sel[i]], 1);
    __syncthreads();
    if (tid == 0) {
        int o = 0;
        for (int e = 0; e < NEXP; e++) { off[e] = o; o += ((cnt[e] + BM - 1) / BM) * BM; }
        off[NEXP] = o;
        int total = o + N_TOK;
        off[NEXP+1] = total;
        int nt = total / BM;
        g_num_tiles = nt;
        for (int t = 0; t < nt; t++) {
            int row = t * BM;
            int e = 0;
            while (e < NEXP+1 && row >= off[e+1]) e++;
            g_tile_exp[t] = e;   // e==8 -> shared-expert slot
        }
    }
    __syncthreads();
    for (int i = tid; i < N_TOK*TOPK; i += 256) {
        int e = g_sel[i];
        int p = off[e] + atomicAdd(&fill[e], 1);
        g_row_tok[p] = i >> 1;
        g_row_wt[p]  = g_wtk[i];
    }
    for (int t = tid; t < N_TOK; t += 256) {
        int p = off[NEXP] + t;
        g_row_tok[p] = t;
        g_row_wt[p]  = 1.0f;
    }
}

// ---------------- 3. convert+transpose weights -> fp16 [slot][N][K] ----------------
__global__ void convert_weights(const float* __restrict__ w1, const float* __restrict__ w2,
                                const float* __restrict__ w3,
                                const float* __restrict__ sw1, const float* __restrict__ sw2,
                                const float* __restrict__ sw3) {
    __shared__ float t[32][33];
    int e = blockIdx.y;                 // 0..8 (8 = shared)
    int mat = blockIdx.z;               // 0=w1, 1=w3, 2=w2
    int tile_r = (blockIdx.x >> 5) << 5;
    int tile_c = (blockIdx.x & 31) << 5;
    const float* src;
    __half* dst;
    size_t eo = (size_t)e << 20;
    if (mat == 0)      { src = (e < 8) ? w1 + eo : sw1; dst = g_w1t + eo; }
    else if (mat == 1) { src = (e < 8) ? w3 + eo : sw3; dst = g_w3t + eo; }
    else               { src = (e < 8) ? w2 + eo : sw2; dst = g_w2t + eo; }

    int tx = threadIdx.x, ty = threadIdx.y;
#pragma unroll
    for (int j = 0; j < 4; j++)
        t[ty + 8*j][tx] = src[(size_t)(tile_r + ty + 8*j) * 1024 + tile_c + tx];
    __syncthreads();
    int l = tx & 15, half = tx >> 4;
#pragma unroll
    for (int j = 0; j < 2; j++) {
        int cy = ty + 8*(2*j + half);
        float v0 = t[2*l][cy], v1 = t[2*l+1][cy];
        uint32_t* d = (uint32_t*)(dst + (size_t)(tile_c + cy) * 1024 + tile_r) + l;
        *d = pack2h(v0, v1);
    }
}

// ---------------- 4. convert x -> fp16 hi/lo ----------------
__global__ void convert_x(const float* __restrict__ x) {
    int i = (blockIdx.x * 256 + threadIdx.x) * 8;
    float4 a = *(const float4*)(x + i);
    float4 b = *(const float4*)(x + i + 4);
    uint4 h = make_uint4(pack2h(a.x, a.y), pack2h(a.z, a.w), pack2h(b.x, b.y), pack2h(b.z, b.w));
    uint4 lo = make_uint4(pack2hlo(a.x, a.y), pack2hlo(a.z, a.w), pack2hlo(b.x, b.y), pack2hlo(b.z, b.w));
    *(uint4*)(g_xh + i) = h;
    *(uint4*)(g_xl + i) = lo;
}

// ---------------- GEMM smem layout constants (bytes) ----------------
#define RS 40
// gemm1 stage: Ah(128x40) Al B1(64x40) B3
#define G1_AH  0
#define G1_AL  10240
#define G1_B1  20480
#define G1_B3  25600
#define G1_STG 30720
// gemm2 stage: Ah Al B
#define G2_AH  0
#define G2_AL  10240
#define G2_B   20480
#define G2_STG 25600

// ---------------- 5. GEMM1: act = silu(x@W1) * (x@W3) ----------------
__global__ void __launch_bounds__(256) gemm1_kernel() {
    extern __shared__ __align__(16) char dyn[];
    __shared__ int toks_sh[BM];

    int tile = blockIdx.x;
    if (tile >= g_num_tiles) return;
    int e  = g_tile_exp[tile];
    int h0 = blockIdx.y * BN;
    int tid = threadIdx.x, lane = tid & 31, wid = tid >> 5;
    int wm = wid & 1, wn = wid >> 1;      // warp tile: 64(m) x 16(n)

    if (tid < BM) toks_sh[tid] = g_row_tok[tile * BM + tid];
    __syncthreads();

    const __half* b1 = g_w1t + ((size_t)e << 20);
    const __half* b3 = g_w3t + ((size_t)e << 20);
    uint32_t smem = smem_u32(dyn);

    int ar0 = (tid*2) >> 2,  ak0 = ((tid*2) & 3) * 8;
    int ar1 = (tid*2+1) >> 2, ak1 = ((tid*2+1) & 3) * 8;
    int br = tid >> 2,       bk = (tid & 3) * 8;
    int atok0 = toks_sh[ar0], atok1 = toks_sh[ar1];
    size_t axo0 = ((size_t)(atok0 < 0 ? 0 : atok0) << 10) + ak0;
    size_t axo1 = ((size_t)(atok1 < 0 ? 0 : atok1) << 10) + ak1;
    int asz0 = atok0 < 0 ? 0 : 16, asz1 = atok1 < 0 ? 0 : 16;
    size_t bro = ((size_t)(h0 + br) << 10) + bk;
    uint32_t adst0 = (uint32_t)(ar0*RS + ak0) * 2;
    uint32_t adst1 = (uint32_t)(ar1*RS + ak1) * 2;
    uint32_t bdst  = (uint32_t)(br*RS + bk) * 2;

#define G1_FILL(k0, sb) do { \
    cp16((sb) + G1_AH + adst0, g_xh + axo0 + (k0), asz0); \
    cp16((sb) + G1_AH + adst1, g_xh + axo1 + (k0), asz1); \
    cp16((sb) + G1_AL + adst0, g_xl + axo0 + (k0), asz0); \
    cp16((sb) + G1_AL + adst1, g_xl + axo1 + (k0), asz1); \
    cp16((sb) + G1_B1 + bdst, b1 + bro + (k0), 16); \
    cp16((sb) + G1_B3 + bdst, b3 + bro + (k0), 16); \
} while (0)

    float acc1[4][2][4], acc3[4][2][4];
#pragma unroll
    for (int i = 0; i < 4; i++)
#pragma unroll
        for (int j = 0; j < 2; j++)
#pragma unroll
            for (int k = 0; k < 4; k++) { acc1[i][j][k] = 0.f; acc3[i][j][k] = 0.f; }

    int lr = lane & 15, lc8 = (lane >> 4) * 8;
    int bbr = lane & 7, bc8 = ((lane >> 3) & 1) * 8;

    G1_FILL(0, smem);
    CP_COMMIT();

    const int NST = DDIM / BK;   // 32
    for (int s = 0; s < NST; s++) {
        if (s + 1 < NST) {
            uint32_t sb = smem + ((s + 1) & 1) * G1_STG;
            G1_FILL((s + 1) * BK, sb);
            CP_COMMIT();
            CP_WAIT(1);
        } else {
            CP_WAIT(0);
        }
        __syncthreads();
        uint32_t sb = smem + (s & 1) * G1_STG;
#pragma unroll
        for (int ks = 0; ks < 2; ks++) {
            uint32_t ah[4][4], al[4][4];
#pragma unroll
            for (int mf = 0; mf < 4; mf++) {
                uint32_t o = (uint32_t)((wm*64 + mf*16 + lr)*RS + ks*16 + lc8) * 2;
                ldm4(ah[mf], sb + G1_AH + o);
                ldm4(al[mf], sb + G1_AL + o);
            }
            uint32_t f1[2][2], f3[2][2];
#pragma unroll
            for (int nf = 0; nf < 2; nf++) {
                uint32_t o = (uint32_t)((wn*16 + nf*8 + bbr)*RS + ks*16 + bc8) * 2;
                ldm2(f1[nf], sb + G1_B1 + o);
                ldm2(f3[nf], sb + G1_B3 + o);
            }
#pragma unroll
            for (int mf = 0; mf < 4; mf++)
#pragma unroll
                for (int nf = 0; nf < 2; nf++) {
                    mma_f16(acc1[mf][nf], ah[mf], f1[nf]);
                    mma_f16(acc1[mf][nf], al[mf], f1[nf]);
                    mma_f16(acc3[mf][nf], ah[mf], f3[nf]);
                    mma_f16(acc3[mf][nf], al[mf], f3[nf]);
                }
        }
        __syncthreads();
    }

    // epilogue: silu(d1)*d3 -> fp16 hi/lo
#pragma unroll
    for (int mf = 0; mf < 4; mf++)
#pragma unroll
        for (int nf = 0; nf < 2; nf++) {
            int m = wm*64 + mf*16 + (lane >> 2);
            int h = h0 + wn*16 + nf*8 + (lane & 3)*2;
            float* c1 = acc1[mf][nf];
            float* c3 = acc3[mf][nf];
#pragma unroll
            for (int half = 0; half < 2; half++) {
                float v1a = c1[half*2], v1b = c1[half*2+1];
                float v3a = c3[half*2], v3b = c3[half*2+1];
                float a0 = (v1a / (1.f + expf(-v1a))) * v3a;
                float a1 = (v1b / (1.f + expf(-v1b))) * v3b;
                size_t row = (size_t)(tile*BM + m + half*8);
                size_t off = (row << 10) + h;
                *(uint32_t*)(g_acth + off) = pack2h(a0, a1);
                *(uint32_t*)(g_actl + off) = pack2hlo(a0, a1);
            }
        }
}

// ---------------- 6. GEMM2: out[tok] += wt * (act @ W2) ----------------
__global__ void __launch_bounds__(256) gemm2_kernel(float* __restrict__ out) {
    extern __shared__ __align__(16) char dyn[];
    __shared__ int   toks_sh[BM];
    __shared__ float wts_sh[BM];

    int tile = blockIdx.x;
    if (tile >= g_num_tiles) return;
    int e  = g_tile_exp[tile];
    int d0 = blockIdx.y * BN;
    int tid = threadIdx.x, lane = tid & 31, wid = tid >> 5;
    int wm = wid & 1, wn = wid >> 1;

    if (tid < BM) {
        toks_sh[tid] = g_row_tok[tile * BM + tid];
        wts_sh[tid]  = g_row_wt[tile * BM + tid];
    }
    __syncthreads();

    const __half* bw = g_w2t + ((size_t)e << 20);
    uint32_t smem = smem_u32(dyn);

    int ar0 = (tid*2) >> 2,  ak0 = ((tid*2) & 3) * 8;
    int ar1 = (tid*2+1) >> 2, ak1 = ((tid*2+1) & 3) * 8;
    int br = tid >> 2,       bk = (tid & 3) * 8;
    size_t axo0 = (((size_t)(tile*BM + ar0)) << 10) + ak0;
    size_t axo1 = (((size_t)(tile*BM + ar1)) << 10) + ak1;
    size_t bro  = ((size_t)(d0 + br) << 10) + bk;
    uint32_t adst0 = (uint32_t)(ar0*RS + ak0) * 2;
    uint32_t adst1 = (uint32_t)(ar1*RS + ak1) * 2;
    uint32_t bdst  = (uint32_t)(br*RS + bk) * 2;

#define G2_FILL(k0, sb) do { \
    cp16((sb) + G2_AH + adst0, g_acth + axo0 + (k0), 16); \
    cp16((sb) + G2_AH + adst1, g_acth + axo1 + (k0), 16); \
    cp16((sb) + G2_AL + adst0, g_actl + axo0 + (k0), 16); \
    cp16((sb) + G2_AL + adst1, g_actl + axo1 + (k0), 16); \
    cp16((sb) + G2_B + bdst, bw + bro + (k0), 16); \
} while (0)

    float acc[4][2][4];
#pragma unroll
    for (int i = 0; i < 4; i++)
#pragma unroll
        for (int j = 0; j < 2; j++)
#pragma unroll
            for (int k = 0; k < 4; k++) acc[i][j][k] = 0.f;

    int lr = lane & 15, lc8 = (lane >> 4) * 8;
    int bbr = lane & 7, bc8 = ((lane >> 3) & 1) * 8;

    G2_FILL(0, smem);
    CP_COMMIT();

    const int NST = HDIM / BK;
    for (int s = 0; s < NST; s++) {
        if (s + 1 < NST) {
            uint32_t sb = smem + ((s + 1) & 1) * G2_STG;
            G2_FILL((s + 1) * BK, sb);
            CP_COMMIT();
            CP_WAIT(1);
        } else {
            CP_WAIT(0);
        }
        __syncthreads();
        uint32_t sb = smem + (s & 1) * G2_STG;
#pragma unroll
        for (int ks = 0; ks < 2; ks++) {
            uint32_t ah[4][4], al[4][4];
#pragma unroll
            for (int mf = 0; mf < 4; mf++) {
                uint32_t o = (uint32_t)((wm*64 + mf*16 + lr)*RS + ks*16 + lc8) * 2;
                ldm4(ah[mf], sb + G2_AH + o);
                ldm4(al[mf], sb + G2_AL + o);
            }
            uint32_t fb[2][2];
#pragma unroll
            for (int nf = 0; nf < 2; nf++) {
                uint32_t o = (uint32_t)((wn*16 + nf*8 + bbr)*RS + ks*16 + bc8) * 2;
                ldm2(fb[nf], sb + G2_B + o);
            }
#pragma unroll
            for (int mf = 0; mf < 4; mf++)
#pragma unroll
                for (int nf = 0; nf < 2; nf++) {
                    mma_f16(acc[mf][nf], ah[mf], fb[nf]);
                    mma_f16(acc[mf][nf], al[mf], fb[nf]);
                }
        }
        __syncthreads();
    }

#pragma unroll
    for (int mf = 0; mf < 4; mf++)
#pragma unroll
        for (int nf = 0; nf < 2; nf++) {
            int m = wm*64 + mf*16 + (lane >> 2);
            int d = d0 + wn*16 + nf*8 + (lane & 3)*2;
            float* c = acc[mf][nf];
#pragma unroll
            for (int half = 0; half < 2; half++) {
                int mr = m + half*8;
                int tok = toks_sh[mr];
                if (tok < 0) continue;
                float wt = wts_sh[mr];
                float* op = out + ((size_t)tok << 10) + d;
                atomicAdd(op,     wt * c[half*2]);
                atomicAdd(op + 1, wt * c[half*2+1]);
            }
        }
}

// ---------------- launch ----------------
extern "C" void kernel_launch(void* const* d_in, const int* in_sizes, int n_in,
                              void* d_out, int out_size) {
    const float* x    = (const float*)d_in[0];
    const float* rw   = (const float*)d_in[1];
    const float* bias = (const float*)d_in[2];
    const float* w1   = (const float*)d_in[3];
    const float* w2   = (const float*)d_in[4];
    const float* w3   = (const float*)d_in[5];
    const float* sw1  = (const float*)d_in[6];
    const float* sw2  = (const float*)d_in[7];
    const float* sw3  = (const float*)d_in[8];
    float* out = (float*)d_out;

    cudaFuncSetAttribute(gemm1_kernel, cudaFuncAttributeMaxDynamicSharedMemorySize, 2*G1_STG);
    cudaFuncSetAttribute(gemm2_kernel, cudaFuncAttributeMaxDynamicSharedMemorySize, 2*G2_STG);

    cudaMemsetAsync(out, 0, (size_t)out_size * sizeof(float));

    dim3 cb(32, 8);
    convert_weights<<<dim3(1024, 9, 3), cb>>>(w1, w2, w3, sw1, sw2, sw3);
    convert_x<<<512, 256>>>(x);
    router_kernel<<<N_TOK/8, 256>>>(x, rw, bias);
    build_kernel<<<1, 256>>>();

    gemm1_kernel<<<dim3(MAX_TILES, HDIM/BN), 256, 2*G1_STG>>>();
    gemm2_kernel<<<dim3(MAX_TILES, DDIM/BN), 256, 2*G2_STG>>>(out);
}

// round 6
// speedup vs baseline: 2.6937x; 1.0073x over previous
#include <cuda_runtime.h>
#include <cuda_fp16.h>
#include <math.h>
#include <stdint.h>

#define N_TOK 1024
#define DDIM  1024
#define HDIM  1024
#define NEXP  8
#define TOPK  2
#define BM    128
#define BN    64
#define BK    64
#define MAX_ROWS  4096
#define MAX_TILES 32

// ---------------- device scratch ----------------
__device__ __half g_w1t[9ull*1024*1024];   // fp16 weights, transposed [slot][N][K]
__device__ __half g_w3t[9ull*1024*1024];
__device__ __half g_w2t[9ull*1024*1024];
__device__ __half g_xh[1024*1024];         // x hi/lo fp16 pair (22-bit x)
__device__ __half g_xl[1024*1024];
__device__ __half g_acth[(size_t)MAX_ROWS*HDIM];
__device__ __half g_actl[(size_t)MAX_ROWS*HDIM];

__device__ int   g_sel[N_TOK*TOPK];
__device__ float g_wtk[N_TOK*TOPK];
__device__ int   g_cnt[NEXP];
__device__ int   g_tile_exp[MAX_TILES];
__device__ int   g_num_tiles;
__device__ int   g_row_tok[MAX_ROWS];
__device__ float g_row_wt[MAX_ROWS];

// ---------------- helpers ----------------
__device__ __forceinline__ uint32_t smem_u32(const void* p) {
    uint32_t a;
    asm("{ .reg .u64 t; cvta.to.shared.u64 t, %1; cvt.u32.u64 %0, t; }" : "=r"(a) : "l"(p));
    return a;
}
__device__ __forceinline__ void cp16(uint32_t dst, const void* src, int sz) {
    asm volatile("cp.async.cg.shared.global [%0], [%1], 16, %2;"
                 :: "r"(dst), "l"(src), "r"(sz) : "memory");
}
#define CP_COMMIT() asm volatile("cp.async.commit_group;" ::: "memory")
#define CP_WAIT(n)  asm volatile("cp.async.wait_group %0;" :: "n"(n) : "memory")

__device__ __forceinline__ void ldm4(uint32_t* r, uint32_t addr) {
    asm volatile("ldmatrix.sync.aligned.m8n8.x4.shared.b16 {%0,%1,%2,%3}, [%4];"
                 : "=r"(r[0]), "=r"(r[1]), "=r"(r[2]), "=r"(r[3]) : "r"(addr));
}
__device__ __forceinline__ void mma_f16(float* d, const uint32_t* a, const uint32_t* b) {
    asm volatile(
        "mma.sync.aligned.m16n8k16.row.col.f32.f16.f16.f32 "
        "{%0,%1,%2,%3},{%4,%5,%6,%7},{%8,%9},{%0,%1,%2,%3};"
        : "+f"(d[0]), "+f"(d[1]), "+f"(d[2]), "+f"(d[3])
        : "r"(a[0]), "r"(a[1]), "r"(a[2]), "r"(a[3]), "r"(b[0]), "r"(b[1]));
}
__device__ __forceinline__ uint32_t pack2h(float a, float b) {
    __half ha = __float2half_rn(a), hb = __float2half_rn(b);
    return (uint32_t)__half_as_ushort(ha) | ((uint32_t)__half_as_ushort(hb) << 16);
}
__device__ __forceinline__ uint32_t pack2hlo(float a, float b) {
    __half ha = __float2half_rn(a), hb = __float2half_rn(b);
    float ra = a - __half2float(ha), rb = b - __half2float(hb);
    return pack2h(ra, rb);
}

// ---------------- 1. convert+transpose weights -> fp16 [slot][N][K]; block0 inits ----------------
__global__ void convert_weights(const float* __restrict__ w1, const float* __restrict__ w2,
                                const float* __restrict__ w3,
                                const float* __restrict__ sw1, const float* __restrict__ sw2,
                                const float* __restrict__ sw3) {
    __shared__ float t[32][33];
    int e = blockIdx.y;                 // 0..8 (8 = shared)
    int mat = blockIdx.z;               // 0=w1, 1=w3, 2=w2
    int tile_r = (blockIdx.x >> 5) << 5;
    int tile_c = (blockIdx.x & 31) << 5;
    const float* src;
    __half* dst;
    size_t eo = (size_t)e << 20;
    if (mat == 0)      { src = (e < 8) ? w1 + eo : sw1; dst = g_w1t + eo; }
    else if (mat == 1) { src = (e < 8) ? w3 + eo : sw3; dst = g_w3t + eo; }
    else               { src = (e < 8) ? w2 + eo : sw2; dst = g_w2t + eo; }

    int tx = threadIdx.x, ty = threadIdx.y;
    int tid = ty * 32 + tx;

    // block (0,0,0): zero expert counters + init padded row list
    if (blockIdx.x == 0 && e == 0 && mat == 0) {
        if (tid < NEXP) g_cnt[tid] = 0;
        for (int i = tid; i < MAX_ROWS; i += 256) { g_row_tok[i] = -1; g_row_wt[i] = 0.f; }
    }

#pragma unroll
    for (int j = 0; j < 4; j++)
        t[ty + 8*j][tx] = src[(size_t)(tile_r + ty + 8*j) * 1024 + tile_c + tx];
    __syncthreads();
    int l = tx & 15, half = tx >> 4;
#pragma unroll
    for (int j = 0; j < 2; j++) {
        int cy = ty + 8*(2*j + half);
        float v0 = t[2*l][cy], v1 = t[2*l+1][cy];
        uint32_t* d = (uint32_t*)(dst + (size_t)(tile_c + cy) * 1024 + tile_r) + l;
        *d = pack2h(v0, v1);
    }
}

// ---------------- 2. router + convert x + count ----------------
__global__ void router_kernel(const float* __restrict__ x,
                              const float* __restrict__ rw,
                              const float* __restrict__ bias) {
    int warp = threadIdx.x >> 5, lane = threadIdx.x & 31;
    int tok = blockIdx.x * 8 + warp;
    if (tok >= N_TOK) return;
    const float* xr = x + (size_t)tok * DDIM;

    float acc[NEXP];
#pragma unroll
    for (int e = 0; e < NEXP; e++) acc[e] = 0.f;
#pragma unroll
    for (int i = 0; i < 8; i++) {
        int d4 = lane + i * 32;            // float4 index within row
        float4 v = ((const float4*)xr)[d4];
        // write x hi/lo fp16
        uint2 h  = make_uint2(pack2h(v.x, v.y), pack2h(v.z, v.w));
        uint2 lo = make_uint2(pack2hlo(v.x, v.y), pack2hlo(v.z, v.w));
        *(uint2*)(g_xh + (size_t)tok * DDIM + d4 * 4) = h;
        *(uint2*)(g_xl + (size_t)tok * DDIM + d4 * 4) = lo;
        // router partial dots
        int d = d4 * 4;
        const float* r0 = rw + (size_t)d * NEXP;
#pragma unroll
        for (int e = 0; e < NEXP; e++)
            acc[e] += v.x * r0[e] + v.y * r0[NEXP + e] + v.z * r0[2*NEXP + e] + v.w * r0[3*NEXP + e];
    }
#pragma unroll
    for (int e = 0; e < NEXP; e++)
#pragma unroll
        for (int o = 16; o > 0; o >>= 1)
            acc[e] += __shfl_xor_sync(0xffffffffu, acc[e], o);
    if (lane == 0) {
        float m = acc[0];
#pragma unroll
        for (int e = 1; e < NEXP; e++) m = fmaxf(m, acc[e]);
        float sc[NEXP]; float s = 0.f;
#pragma unroll
        for (int e = 0; e < NEXP; e++) { sc[e] = expf(acc[e] - m); s += sc[e]; }
        float inv = 1.f / s;
#pragma unroll
        for (int e = 0; e < NEXP; e++) sc[e] *= inv;
        int i0 = 0; float b0 = sc[0] + bias[0];
#pragma unroll
        for (int e = 1; e < NEXP; e++) { float v = sc[e] + bias[e]; if (v > b0) { b0 = v; i0 = e; } }
        int i1 = -1; float b1 = -1e30f;
#pragma unroll
        for (int e = 0; e < NEXP; e++) {
            if (e == i0) continue;
            float v = sc[e] + bias[e]; if (v > b1) { b1 = v; i1 = e; }
        }
        g_sel[tok*2]   = i0;  g_sel[tok*2+1] = i1;
        g_wtk[tok*2]   = sc[i0]; g_wtk[tok*2+1] = sc[i1];
        atomicAdd(&g_cnt[i0], 1);
        atomicAdd(&g_cnt[i1], 1);
    }
}

// ---------------- 3. build: offsets + scatter (rows pre-initialized) ----------------
__global__ void build_kernel() {
    __shared__ int off[NEXP+2], fill[NEXP];
    int tid = threadIdx.x;
    if (tid < NEXP) fill[tid] = 0;
    if (tid == 0) {
        int o = 0;
        for (int e = 0; e < NEXP; e++) { off[e] = o; o += ((g_cnt[e] + BM - 1) / BM) * BM; }
        off[NEXP] = o;
        int total = o + N_TOK;
        off[NEXP+1] = total;
        int nt = total / BM;
        g_num_tiles = nt;
        for (int t = 0; t < nt; t++) {
            int row = t * BM;
            int e = 0;
            while (e < NEXP+1 && row >= off[e+1]) e++;
            g_tile_exp[t] = e;   // e==8 -> shared-expert slot
        }
    }
    __syncthreads();
    for (int i = tid; i < N_TOK*TOPK; i += 256) {
        int e = g_sel[i];
        int p = off[e] + atomicAdd(&fill[e], 1);
        g_row_tok[p] = i >> 1;
        g_row_wt[p]  = g_wtk[i];
    }
    for (int t = tid; t < N_TOK; t += 256) {
        int p = off[NEXP] + t;
        g_row_tok[p] = t;
        g_row_wt[p]  = 1.0f;
    }
}

// ---------------- GEMM smem layout constants ----------------
#define RS 72                       // elems per row (64 + 8 pad), 144 B stride
#define G1_AH  0
#define G1_AL  18432                // 128*72*2
#define G1_B1  36864
#define G1_B3  46080                // +64*72*2
#define G1_STG 55296
#define G2_AH  0
#define G2_AL  18432
#define G2_B   36864
#define G2_STG 46080

// ---------------- 4. GEMM1: act = silu(x@W1) * (x@W3) ----------------
__global__ void __launch_bounds__(256) gemm1_kernel() {
    extern __shared__ __align__(16) char dyn[];
    __shared__ int toks_sh[BM];

    int tile = blockIdx.x;
    if (tile >= g_num_tiles) return;
    int e  = g_tile_exp[tile];
    int h0 = blockIdx.y * BN;
    int tid = threadIdx.x, lane = tid & 31, wid = tid >> 5;
    int wm = wid & 1, wn = wid >> 1;      // warp tile: 64(m) x 16(n)

    if (tid < BM) toks_sh[tid] = g_row_tok[tile * BM + tid];
    __syncthreads();

    const __half* b1 = g_w1t + ((size_t)e << 20);
    const __half* b3 = g_w3t + ((size_t)e << 20);
    uint32_t smem = smem_u32(dyn);

    // fill coords: 4 A-chunks + 2 B-chunks per thread (BK=64)
    int frow = tid >> 3, fk = (tid & 3 << 0, (tid & 7) * 8);
    fk = (tid & 7) * 8;
    size_t axo[4]; uint32_t adst[4]; int asz[4];
#pragma unroll
    for (int it = 0; it < 4; it++) {
        int row = frow + 32 * it;
        int tok = toks_sh[row];
        axo[it]  = ((size_t)(tok < 0 ? 0 : tok) << 10) + fk;
        asz[it]  = tok < 0 ? 0 : 16;
        adst[it] = (uint32_t)(row * RS + fk) * 2;
    }
    size_t bro[2]; uint32_t bdst[2];
#pragma unroll
    for (int it = 0; it < 2; it++) {
        int row = frow + 32 * it;      // 0..63
        bro[it]  = ((size_t)(h0 + row) << 10) + fk;
        bdst[it] = (uint32_t)(row * RS + fk) * 2;
    }

#define G1_FILL(k0, sb) do { \
    cp16((sb) + G1_AH + adst[0], g_xh + axo[0] + (k0), asz[0]); \
    cp16((sb) + G1_AH + adst[1], g_xh + axo[1] + (k0), asz[1]); \
    cp16((sb) + G1_AH + adst[2], g_xh + axo[2] + (k0), asz[2]); \
    cp16((sb) + G1_AH + adst[3], g_xh + axo[3] + (k0), asz[3]); \
    cp16((sb) + G1_AL + adst[0], g_xl + axo[0] + (k0), asz[0]); \
    cp16((sb) + G1_AL + adst[1], g_xl + axo[1] + (k0), asz[1]); \
    cp16((sb) + G1_AL + adst[2], g_xl + axo[2] + (k0), asz[2]); \
    cp16((sb) + G1_AL + adst[3], g_xl + axo[3] + (k0), asz[3]); \
    cp16((sb) + G1_B1 + bdst[0], b1 + bro[0] + (k0), 16); \
    cp16((sb) + G1_B1 + bdst[1], b1 + bro[1] + (k0), 16); \
    cp16((sb) + G1_B3 + bdst[0], b3 + bro[0] + (k0), 16); \
    cp16((sb) + G1_B3 + bdst[1], b3 + bro[1] + (k0), 16); \
} while (0)

    float acc1[4][2][4], acc3[4][2][4];
#pragma unroll
    for (int i = 0; i < 4; i++)
#pragma unroll
        for (int j = 0; j < 2; j++)
#pragma unroll
            for (int k = 0; k < 4; k++) { acc1[i][j][k] = 0.f; acc3[i][j][k] = 0.f; }

    // ldmatrix lane addressing
    int lr = lane & 15, lc8 = (lane >> 4) * 8;                       // A x4
    uint32_t bbase = (uint32_t)((wn*16 + ((lane >> 4) << 3) + (lane & 7)) * RS
                   + (((lane >> 3) & 1) * 8));                        // B x4 (2 n-blocks)

    G1_FILL(0, smem);
    CP_COMMIT();

    const int NST = DDIM / BK;   // 16
    for (int s = 0; s < NST; s++) {
        if (s + 1 < NST) {
            uint32_t sb = smem + ((s + 1) & 1) * G1_STG;
            G1_FILL((s + 1) * BK, sb);
            CP_COMMIT();
            CP_WAIT(1);
        } else {
            CP_WAIT(0);
        }
        __syncthreads();
        uint32_t sb = smem + (s & 1) * G1_STG;
#pragma unroll
        for (int ks = 0; ks < 4; ks++) {
            uint32_t ah[4][4], al[4][4];
#pragma unroll
            for (int mf = 0; mf < 4; mf++) {
                uint32_t o = (uint32_t)((wm*64 + mf*16 + lr)*RS + ks*16 + lc8) * 2;
                ldm4(ah[mf], sb + G1_AH + o);
                ldm4(al[mf], sb + G1_AL + o);
            }
            uint32_t f1[4], f3[4];
            {
                uint32_t o = (bbase + ks*16) * 2;
                ldm4(f1, sb + G1_B1 + o);
                ldm4(f3, sb + G1_B3 + o);
            }
#pragma unroll
            for (int mf = 0; mf < 4; mf++)
#pragma unroll
                for (int nf = 0; nf < 2; nf++) {
                    mma_f16(acc1[mf][nf], ah[mf], f1 + nf*2);
                    mma_f16(acc1[mf][nf], al[mf], f1 + nf*2);
                    mma_f16(acc3[mf][nf], ah[mf], f3 + nf*2);
                    mma_f16(acc3[mf][nf], al[mf], f3 + nf*2);
                }
        }
        __syncthreads();
    }

    // epilogue: silu(d1)*d3 -> fp16 hi/lo
#pragma unroll
    for (int mf = 0; mf < 4; mf++)
#pragma unroll
        for (int nf = 0; nf < 2; nf++) {
            int m = wm*64 + mf*16 + (lane >> 2);
            int h = h0 + wn*16 + nf*8 + (lane & 3)*2;
            float* c1 = acc1[mf][nf];
            float* c3 = acc3[mf][nf];
#pragma unroll
            for (int half = 0; half < 2; half++) {
                float v1a = c1[half*2], v1b = c1[half*2+1];
                float v3a = c3[half*2], v3b = c3[half*2+1];
                float a0 = (v1a / (1.f + expf(-v1a))) * v3a;
                float a1 = (v1b / (1.f + expf(-v1b))) * v3b;
                size_t row = (size_t)(tile*BM + m + half*8);
                size_t off = (row << 10) + h;
                *(uint32_t*)(g_acth + off) = pack2h(a0, a1);
                *(uint32_t*)(g_actl + off) = pack2hlo(a0, a1);
            }
        }
}

// ---------------- 5. GEMM2: out[tok] += wt * (act @ W2) ----------------
__global__ void __launch_bounds__(256) gemm2_kernel(float* __restrict__ out) {
    extern __shared__ __align__(16) char dyn[];
    __shared__ int   toks_sh[BM];
    __shared__ float wts_sh[BM];

    int tile = blockIdx.x;
    if (tile >= g_num_tiles) return;
    int e  = g_tile_exp[tile];
    int d0 = blockIdx.y * BN;
    int tid = threadIdx.x, lane = tid & 31, wid = tid >> 5;
    int wm = wid & 1, wn = wid >> 1;

    if (tid < BM) {
        toks_sh[tid] = g_row_tok[tile * BM + tid];
        wts_sh[tid]  = g_row_wt[tile * BM + tid];
    }
    __syncthreads();

    const __half* bw = g_w2t + ((size_t)e << 20);
    uint32_t smem = smem_u32(dyn);

    int frow = tid >> 3;
    int fk = (tid & 7) * 8;
    size_t axo[4]; uint32_t adst[4];
#pragma unroll
    for (int it = 0; it < 4; it++) {
        int row = frow + 32 * it;
        axo[it]  = (((size_t)(tile*BM + row)) << 10) + fk;
        adst[it] = (uint32_t)(row * RS + fk) * 2;
    }
    size_t bro[2]; uint32_t bdst[2];
#pragma unroll
    for (int it = 0; it < 2; it++) {
        int row = frow + 32 * it;
        bro[it]  = ((size_t)(d0 + row) << 10) + fk;
        bdst[it] = (uint32_t)(row * RS + fk) * 2;
    }

#define G2_FILL(k0, sb) do { \
    cp16((sb) + G2_AH + adst[0], g_acth + axo[0] + (k0), 16); \
    cp16((sb) + G2_AH + adst[1], g_acth + axo[1] + (k0), 16); \
    cp16((sb) + G2_AH + adst[2], g_acth + axo[2] + (k0), 16); \
    cp16((sb) + G2_AH + adst[3], g_acth + axo[3] + (k0), 16); \
    cp16((sb) + G2_AL + adst[0], g_actl + axo[0] + (k0), 16); \
    cp16((sb) + G2_AL + adst[1], g_actl + axo[1] + (k0), 16); \
    cp16((sb) + G2_AL + adst[2], g_actl + axo[2] + (k0), 16); \
    cp16((sb) + G2_AL + adst[3], g_actl + axo[3] + (k0), 16); \
    cp16((sb) + G2_B + bdst[0], bw + bro[0] + (k0), 16); \
    cp16((sb) + G2_B + bdst[1], bw + bro[1] + (k0), 16); \
} while (0)

    float acc[4][2][4];
#pragma unroll
    for (int i = 0; i < 4; i++)
#pragma unroll
        for (int j = 0; j < 2; j++)
#pragma unroll
            for (int k = 0; k < 4; k++) acc[i][j][k] = 0.f;

    int lr = lane & 15, lc8 = (lane >> 4) * 8;
    uint32_t bbase = (uint32_t)((wn*16 + ((lane >> 4) << 3) + (lane & 7)) * RS
                   + (((lane >> 3) & 1) * 8));

    G2_FILL(0, smem);
    CP_COMMIT();

    const int NST = HDIM / BK;
    for (int s = 0; s < NST; s++) {
        if (s + 1 < NST) {
            uint32_t sb = smem + ((s + 1) & 1) * G2_STG;
            G2_FILL((s + 1) * BK, sb);
            CP_COMMIT();
            CP_WAIT(1);
        } else {
            CP_WAIT(0);
        }
        __syncthreads();
        uint32_t sb = smem + (s & 1) * G2_STG;
#pragma unroll
        for (int ks = 0; ks < 4; ks++) {
            uint32_t ah[4][4], al[4][4];
#pragma unroll
            for (int mf = 0; mf < 4; mf++) {
                uint32_t o = (uint32_t)((wm*64 + mf*16 + lr)*RS + ks*16 + lc8) * 2;
                ldm4(ah[mf], sb + G2_AH + o);
                ldm4(al[mf], sb + G2_AL + o);
            }
            uint32_t fb[4];
            {
                uint32_t o = (bbase + ks*16) * 2;
                ldm4(fb, sb + G2_B + o);
            }
#pragma unroll
            for (int mf = 0; mf < 4; mf++)
#pragma unroll
                for (int nf = 0; nf < 2; nf++) {
                    mma_f16(acc[mf][nf], ah[mf], fb + nf*2);
                    mma_f16(acc[mf][nf], al[mf], fb + nf*2);
                }
        }
        __syncthreads();
    }

#pragma unroll
    for (int mf = 0; mf < 4; mf++)
#pragma unroll
        for (int nf = 0; nf < 2; nf++) {
            int m = wm*64 + mf*16 + (lane >> 2);
            int d = d0 + wn*16 + nf*8 + (lane & 3)*2;
            float* c = acc[mf][nf];
#pragma unroll
            for (int half = 0; half < 2; half++) {
                int mr = m + half*8;
                int tok = toks_sh[mr];
                if (tok < 0) continue;
                float wt = wts_sh[mr];
                float* op = out + ((size_t)tok << 10) + d;
                atomicAdd(op,     wt * c[half*2]);
                atomicAdd(op + 1, wt * c[half*2+1]);
            }
        }
}

// ---------------- launch ----------------
extern "C" void kernel_launch(void* const* d_in, const int* in_sizes, int n_in,
                              void* d_out, int out_size) {
    const float* x    = (const float*)d_in[0];
    const float* rw   = (const float*)d_in[1];
    const float* bias = (const float*)d_in[2];
    const float* w1   = (const float*)d_in[3];
    const float* w2   = (const float*)d_in[4];
    const float* w3   = (const float*)d_in[5];
    const float* sw1  = (const float*)d_in[6];
    const float* sw2  = (const float*)d_in[7];
    const float* sw3  = (const float*)d_in[8];
    float* out = (float*)d_out;

    cudaFuncSetAttribute(gemm1_kernel, cudaFuncAttributeMaxDynamicSharedMemorySize, 2*G1_STG);
    cudaFuncSetAttribute(gemm2_kernel, cudaFuncAttributeMaxDynamicSharedMemorySize, 2*G2_STG);

    cudaMemsetAsync(out, 0, (size_t)out_size * sizeof(float));

    dim3 cb(32, 8);
    convert_weights<<<dim3(1024, 9, 3), cb>>>(w1, w2, w3, sw1, sw2, sw3);
    router_kernel<<<N_TOK/8, 256>>>(x, rw, bias);
    build_kernel<<<1, 256>>>();

    gemm1_kernel<<<dim3(MAX_TILES, HDIM/BN), 256, 2*G1_STG>>>();
    gemm2_kernel<<<dim3(MAX_TILES, DDIM/BN), 256, 2*G2_STG>>>(out);
}

// round 7
// speedup vs baseline: 2.9885x; 1.1094x over previous
#include <cuda_runtime.h>
#include <cuda_fp16.h>
#include <math.h>
#include <stdint.h>

#define N_TOK 1024
#define DDIM  1024
#define HDIM  1024
#define NEXP  8
#define TOPK  2
#define BM    128
#define BN    64
#define BK    64
#define MAX_ROWS  4096
#define MAX_TILES 32

// ---------------- device scratch ----------------
__device__ __half g_w1t[9ull*1024*1024];   // fp16 weights, transposed [slot][N][K]
__device__ __half g_w3t[9ull*1024*1024];
__device__ __half g_w2t[9ull*1024*1024];
__device__ __half g_xh[1024*1024];         // x hi/lo fp16 pair (22-bit x)
__device__ __half g_xl[1024*1024];
__device__ __half g_acth[(size_t)MAX_ROWS*HDIM];

__device__ int   g_sel[N_TOK*TOPK];
__device__ float g_wtk[N_TOK*TOPK];
__device__ int   g_cnt[NEXP];
__device__ int   g_tile_exp[MAX_TILES];
__device__ int   g_num_tiles;
__device__ int   g_row_tok[MAX_ROWS];
__device__ float g_row_wt[MAX_ROWS];

// ---------------- helpers ----------------
__device__ __forceinline__ uint32_t smem_u32(const void* p) {
    uint32_t a;
    asm("{ .reg .u64 t; cvta.to.shared.u64 t, %1; cvt.u32.u64 %0, t; }" : "=r"(a) : "l"(p));
    return a;
}
__device__ __forceinline__ void cp16(uint32_t dst, const void* src, int sz) {
    asm volatile("cp.async.cg.shared.global [%0], [%1], 16, %2;"
                 :: "r"(dst), "l"(src), "r"(sz) : "memory");
}
#define CP_COMMIT() asm volatile("cp.async.commit_group;" ::: "memory")
#define CP_WAIT(n)  asm volatile("cp.async.wait_group %0;" :: "n"(n) : "memory")

__device__ __forceinline__ void ldm4(uint32_t* r, uint32_t addr) {
    asm volatile("ldmatrix.sync.aligned.m8n8.x4.shared.b16 {%0,%1,%2,%3}, [%4];"
                 : "=r"(r[0]), "=r"(r[1]), "=r"(r[2]), "=r"(r[3]) : "r"(addr));
}
__device__ __forceinline__ void mma_f16(float* d, const uint32_t* a, const uint32_t* b) {
    asm volatile(
        "mma.sync.aligned.m16n8k16.row.col.f32.f16.f16.f32 "
        "{%0,%1,%2,%3},{%4,%5,%6,%7},{%8,%9},{%0,%1,%2,%3};"
        : "+f"(d[0]), "+f"(d[1]), "+f"(d[2]), "+f"(d[3])
        : "r"(a[0]), "r"(a[1]), "r"(a[2]), "r"(a[3]), "r"(b[0]), "r"(b[1]));
}
__device__ __forceinline__ uint32_t pack2h(float a, float b) {
    __half ha = __float2half_rn(a), hb = __float2half_rn(b);
    return (uint32_t)__half_as_ushort(ha) | ((uint32_t)__half_as_ushort(hb) << 16);
}
__device__ __forceinline__ uint32_t pack2hlo(float a, float b) {
    __half ha = __float2half_rn(a), hb = __float2half_rn(b);
    float ra = a - __half2float(ha), rb = b - __half2float(hb);
    return pack2h(ra, rb);
}

// ---------------- 1. convert+transpose weights -> fp16 [slot][N][K]; block0 inits ----------------
__global__ void convert_weights(const float* __restrict__ w1, const float* __restrict__ w2,
                                const float* __restrict__ w3,
                                const float* __restrict__ sw1, const float* __restrict__ sw2,
                                const float* __restrict__ sw3) {
    __shared__ float t[32][33];
    int e = blockIdx.y;                 // 0..8 (8 = shared)
    int mat = blockIdx.z;               // 0=w1, 1=w3, 2=w2
    int tile_r = (blockIdx.x >> 5) << 5;
    int tile_c = (blockIdx.x & 31) << 5;
    const float* src;
    __half* dst;
    size_t eo = (size_t)e << 20;
    if (mat == 0)      { src = (e < 8) ? w1 + eo : sw1; dst = g_w1t + eo; }
    else if (mat == 1) { src = (e < 8) ? w3 + eo : sw3; dst = g_w3t + eo; }
    else               { src = (e < 8) ? w2 + eo : sw2; dst = g_w2t + eo; }

    int tx = threadIdx.x, ty = threadIdx.y;
    int tid = ty * 32 + tx;

    if (blockIdx.x == 0 && e == 0 && mat == 0) {
        if (tid < NEXP) g_cnt[tid] = 0;
        for (int i = tid; i < MAX_ROWS; i += 256) { g_row_tok[i] = -1; g_row_wt[i] = 0.f; }
    }

#pragma unroll
    for (int j = 0; j < 4; j++)
        t[ty + 8*j][tx] = src[(size_t)(tile_r + ty + 8*j) * 1024 + tile_c + tx];
    __syncthreads();
    int l = tx & 15, half = tx >> 4;
#pragma unroll
    for (int j = 0; j < 2; j++) {
        int cy = ty + 8*(2*j + half);
        float v0 = t[2*l][cy], v1 = t[2*l+1][cy];
        uint32_t* d = (uint32_t*)(dst + (size_t)(tile_c + cy) * 1024 + tile_r) + l;
        *d = pack2h(v0, v1);
    }
}

// ---------------- 2. router + convert x + count ----------------
__global__ void router_kernel(const float* __restrict__ x,
                              const float* __restrict__ rw,
                              const float* __restrict__ bias) {
    int warp = threadIdx.x >> 5, lane = threadIdx.x & 31;
    int tok = blockIdx.x * 8 + warp;
    if (tok >= N_TOK) return;
    const float* xr = x + (size_t)tok * DDIM;

    float acc[NEXP];
#pragma unroll
    for (int e = 0; e < NEXP; e++) acc[e] = 0.f;
#pragma unroll
    for (int i = 0; i < 8; i++) {
        int d4 = lane + i * 32;
        float4 v = ((const float4*)xr)[d4];
        uint2 h  = make_uint2(pack2h(v.x, v.y), pack2h(v.z, v.w));
        uint2 lo = make_uint2(pack2hlo(v.x, v.y), pack2hlo(v.z, v.w));
        *(uint2*)(g_xh + (size_t)tok * DDIM + d4 * 4) = h;
        *(uint2*)(g_xl + (size_t)tok * DDIM + d4 * 4) = lo;
        int d = d4 * 4;
        const float* r0 = rw + (size_t)d * NEXP;
#pragma unroll
        for (int e = 0; e < NEXP; e++)
            acc[e] += v.x * r0[e] + v.y * r0[NEXP + e] + v.z * r0[2*NEXP + e] + v.w * r0[3*NEXP + e];
    }
#pragma unroll
    for (int e = 0; e < NEXP; e++)
#pragma unroll
        for (int o = 16; o > 0; o >>= 1)
            acc[e] += __shfl_xor_sync(0xffffffffu, acc[e], o);
    if (lane == 0) {
        float m = acc[0];
#pragma unroll
        for (int e = 1; e < NEXP; e++) m = fmaxf(m, acc[e]);
        float sc[NEXP]; float s = 0.f;
#pragma unroll
        for (int e = 0; e < NEXP; e++) { sc[e] = expf(acc[e] - m); s += sc[e]; }
        float inv = 1.f / s;
#pragma unroll
        for (int e = 0; e < NEXP; e++) sc[e] *= inv;
        int i0 = 0; float b0 = sc[0] + bias[0];
#pragma unroll
        for (int e = 1; e < NEXP; e++) { float v = sc[e] + bias[e]; if (v > b0) { b0 = v; i0 = e; } }
        int i1 = -1; float b1 = -1e30f;
#pragma unroll
        for (int e = 0; e < NEXP; e++) {
            if (e == i0) continue;
            float v = sc[e] + bias[e]; if (v > b1) { b1 = v; i1 = e; }
        }
        g_sel[tok*2]   = i0;  g_sel[tok*2+1] = i1;
        g_wtk[tok*2]   = sc[i0]; g_wtk[tok*2+1] = sc[i1];
        atomicAdd(&g_cnt[i0], 1);
        atomicAdd(&g_cnt[i1], 1);
    }
}

// ---------------- 3. build: offsets + scatter ----------------
__global__ void build_kernel() {
    __shared__ int off[NEXP+2], fill[NEXP];
    int tid = threadIdx.x;
    if (tid < NEXP) fill[tid] = 0;
    if (tid == 0) {
        int o = 0;
        for (int e = 0; e < NEXP; e++) { off[e] = o; o += ((g_cnt[e] + BM - 1) / BM) * BM; }
        off[NEXP] = o;
        int total = o + N_TOK;
        off[NEXP+1] = total;
        int nt = total / BM;
        g_num_tiles = nt;
        for (int t = 0; t < nt; t++) {
            int row = t * BM;
            int e = 0;
            while (e < NEXP+1 && row >= off[e+1]) e++;
            g_tile_exp[t] = e;   // e==8 -> shared-expert slot
        }
    }
    __syncthreads();
    for (int i = tid; i < N_TOK*TOPK; i += 256) {
        int e = g_sel[i];
        int p = off[e] + atomicAdd(&fill[e], 1);
        g_row_tok[p] = i >> 1;
        g_row_wt[p]  = g_wtk[i];
    }
    for (int t = tid; t < N_TOK; t += 256) {
        int p = off[NEXP] + t;
        g_row_tok[p] = t;
        g_row_wt[p]  = 1.0f;
    }
}

// ---------------- GEMM smem layout constants ----------------
#define RS 72                       // elems per row (64 + 8 pad), 144 B stride
#define G1_AH  0
#define G1_AL  18432                // 128*72*2
#define G1_B1  36864
#define G1_B3  46080
#define G1_STG 55296
#define G2_A   0
#define G2_B   18432
#define G2_STG 27648

// ---------------- 4. GEMM1: act = silu(x@W1) * (x@W3) ----------------
__global__ void __launch_bounds__(256, 2) gemm1_kernel() {
    extern __shared__ __align__(16) char dyn[];
    __shared__ int toks_sh[BM];

    int tile = blockIdx.x;
    if (tile >= g_num_tiles) return;
    int e  = g_tile_exp[tile];
    int h0 = blockIdx.y * BN;
    int tid = threadIdx.x, lane = tid & 31, wid = tid >> 5;
    int wm = wid & 1, wn = wid >> 1;      // warp tile: 64(m) x 16(n)

    if (tid < BM) toks_sh[tid] = g_row_tok[tile * BM + tid];
    __syncthreads();

    const __half* b1 = g_w1t + ((size_t)e << 20);
    const __half* b3 = g_w3t + ((size_t)e << 20);
    uint32_t smem = smem_u32(dyn);

    int frow = tid >> 3;
    int fk = (tid & 7) * 8;
    size_t axo[4]; uint32_t adst[4]; int asz[4];
#pragma unroll
    for (int it = 0; it < 4; it++) {
        int row = frow + 32 * it;
        int tok = toks_sh[row];
        axo[it]  = ((size_t)(tok < 0 ? 0 : tok) << 10) + fk;
        asz[it]  = tok < 0 ? 0 : 16;
        adst[it] = (uint32_t)(row * RS + fk) * 2;
    }
    size_t bro[2]; uint32_t bdst[2];
#pragma unroll
    for (int it = 0; it < 2; it++) {
        int row = frow + 32 * it;
        bro[it]  = ((size_t)(h0 + row) << 10) + fk;
        bdst[it] = (uint32_t)(row * RS + fk) * 2;
    }

#define G1_FILL(k0, sb) do { \
    cp16((sb) + G1_AH + adst[0], g_xh + axo[0] + (k0), asz[0]); \
    cp16((sb) + G1_AH + adst[1], g_xh + axo[1] + (k0), asz[1]); \
    cp16((sb) + G1_AH + adst[2], g_xh + axo[2] + (k0), asz[2]); \
    cp16((sb) + G1_AH + adst[3], g_xh + axo[3] + (k0), asz[3]); \
    cp16((sb) + G1_AL + adst[0], g_xl + axo[0] + (k0), asz[0]); \
    cp16((sb) + G1_AL + adst[1], g_xl + axo[1] + (k0), asz[1]); \
    cp16((sb) + G1_AL + adst[2], g_xl + axo[2] + (k0), asz[2]); \
    cp16((sb) + G1_AL + adst[3], g_xl + axo[3] + (k0), asz[3]); \
    cp16((sb) + G1_B1 + bdst[0], b1 + bro[0] + (k0), 16); \
    cp16((sb) + G1_B1 + bdst[1], b1 + bro[1] + (k0), 16); \
    cp16((sb) + G1_B3 + bdst[0], b3 + bro[0] + (k0), 16); \
    cp16((sb) + G1_B3 + bdst[1], b3 + bro[1] + (k0), 16); \
} while (0)

    float acc1[4][2][4], acc3[4][2][4];
#pragma unroll
    for (int i = 0; i < 4; i++)
#pragma unroll
        for (int j = 0; j < 2; j++)
#pragma unroll
            for (int k = 0; k < 4; k++) { acc1[i][j][k] = 0.f; acc3[i][j][k] = 0.f; }

    int lr = lane & 15, lc8 = (lane >> 4) * 8;
    uint32_t bbase = (uint32_t)((wn*16 + ((lane >> 4) << 3) + (lane & 7)) * RS
                   + (((lane >> 3) & 1) * 8));

    G1_FILL(0, smem);
    CP_COMMIT();

    const int NST = DDIM / BK;   // 16
    for (int s = 0; s < NST; s++) {
        if (s + 1 < NST) {
            uint32_t sb = smem + ((s + 1) & 1) * G1_STG;
            G1_FILL((s + 1) * BK, sb);
            CP_COMMIT();
            CP_WAIT(1);
        } else {
            CP_WAIT(0);
        }
        __syncthreads();
        uint32_t sb = smem + (s & 1) * G1_STG;
#pragma unroll
        for (int ks = 0; ks < 4; ks++) {
            uint32_t ah[4][4], al[4][4];
#pragma unroll
            for (int mf = 0; mf < 4; mf++) {
                uint32_t o = (uint32_t)((wm*64 + mf*16 + lr)*RS + ks*16 + lc8) * 2;
                ldm4(ah[mf], sb + G1_AH + o);
                ldm4(al[mf], sb + G1_AL + o);
            }
            uint32_t f1[4], f3[4];
            {
                uint32_t o = (bbase + ks*16) * 2;
                ldm4(f1, sb + G1_B1 + o);
                ldm4(f3, sb + G1_B3 + o);
            }
#pragma unroll
            for (int mf = 0; mf < 4; mf++)
#pragma unroll
                for (int nf = 0; nf < 2; nf++) {
                    mma_f16(acc1[mf][nf], ah[mf], f1 + nf*2);
                    mma_f16(acc1[mf][nf], al[mf], f1 + nf*2);
                    mma_f16(acc3[mf][nf], ah[mf], f3 + nf*2);
                    mma_f16(acc3[mf][nf], al[mf], f3 + nf*2);
                }
        }
        __syncthreads();
    }

    // epilogue: silu(d1)*d3 -> fp16 (single precision-term act)
#pragma unroll
    for (int mf = 0; mf < 4; mf++)
#pragma unroll
        for (int nf = 0; nf < 2; nf++) {
            int m = wm*64 + mf*16 + (lane >> 2);
            int h = h0 + wn*16 + nf*8 + (lane & 3)*2;
            float* c1 = acc1[mf][nf];
            float* c3 = acc3[mf][nf];
#pragma unroll
            for (int half = 0; half < 2; half++) {
                float v1a = c1[half*2], v1b = c1[half*2+1];
                float v3a = c3[half*2], v3b = c3[half*2+1];
                float a0 = (v1a / (1.f + expf(-v1a))) * v3a;
                float a1 = (v1b / (1.f + expf(-v1b))) * v3b;
                size_t row = (size_t)(tile*BM + m + half*8);
                *(uint32_t*)(g_acth + (row << 10) + h) = pack2h(a0, a1);
            }
        }
}

// ---------------- 5. GEMM2: out[tok] += wt * (act @ W2) ----------------
__global__ void __launch_bounds__(256, 2) gemm2_kernel(float* __restrict__ out) {
    extern __shared__ __align__(16) char dyn[];
    __shared__ int   toks_sh[BM];
    __shared__ float wts_sh[BM];

    int tile = blockIdx.x;
    if (tile >= g_num_tiles) return;
    int e  = g_tile_exp[tile];
    int d0 = blockIdx.y * BN;
    int tid = threadIdx.x, lane = tid & 31, wid = tid >> 5;
    int wm = wid & 1, wn = wid >> 1;

    if (tid < BM) {
        toks_sh[tid] = g_row_tok[tile * BM + tid];
        wts_sh[tid]  = g_row_wt[tile * BM + tid];
    }
    __syncthreads();

    const __half* bw = g_w2t + ((size_t)e << 20);
    uint32_t smem = smem_u32(dyn);

    int frow = tid >> 3;
    int fk = (tid & 7) * 8;
    size_t axo[4]; uint32_t adst[4];
#pragma unroll
    for (int it = 0; it < 4; it++) {
        int row = frow + 32 * it;
        axo[it]  = (((size_t)(tile*BM + row)) << 10) + fk;
        adst[it] = (uint32_t)(row * RS + fk) * 2;
    }
    size_t bro[2]; uint32_t bdst[2];
#pragma unroll
    for (int it = 0; it < 2; it++) {
        int row = frow + 32 * it;
        bro[it]  = ((size_t)(d0 + row) << 10) + fk;
        bdst[it] = (uint32_t)(row * RS + fk) * 2;
    }

#define G2_FILL(k0, sb) do { \
    cp16((sb) + G2_A + adst[0], g_acth + axo[0] + (k0), 16); \
    cp16((sb) + G2_A + adst[1], g_acth + axo[1] + (k0), 16); \
    cp16((sb) + G2_A + adst[2], g_acth + axo[2] + (k0), 16); \
    cp16((sb) + G2_A + adst[3], g_acth + axo[3] + (k0), 16); \
    cp16((sb) + G2_B + bdst[0], bw + bro[0] + (k0), 16); \
    cp16((sb) + G2_B + bdst[1], bw + bro[1] + (k0), 16); \
} while (0)

    float acc[4][2][4];
#pragma unroll
    for (int i = 0; i < 4; i++)
#pragma unroll
        for (int j = 0; j < 2; j++)
#pragma unroll
            for (int k = 0; k < 4; k++) acc[i][j][k] = 0.f;

    int lr = lane & 15, lc8 = (lane >> 4) * 8;
    uint32_t bbase = (uint32_t)((wn*16 + ((lane >> 4) << 3) + (lane & 7)) * RS
                   + (((lane >> 3) & 1) * 8));

    G2_FILL(0, smem);
    CP_COMMIT();

    const int NST = HDIM / BK;
    for (int s = 0; s < NST; s++) {
        if (s + 1 < NST) {
            uint32_t sb = smem + ((s + 1) & 1) * G2_STG;
            G2_FILL((s + 1) * BK, sb);
            CP_COMMIT();
            CP_WAIT(1);
        } else {
            CP_WAIT(0);
        }
        __syncthreads();
        uint32_t sb = smem + (s & 1) * G2_STG;
#pragma unroll
        for (int ks = 0; ks < 4; ks++) {
            uint32_t ah[4][4];
#pragma unroll
            for (int mf = 0; mf < 4; mf++) {
                uint32_t o = (uint32_t)((wm*64 + mf*16 + lr)*RS + ks*16 + lc8) * 2;
                ldm4(ah[mf], sb + G2_A + o);
            }
            uint32_t fb[4];
            {
                uint32_t o = (bbase + ks*16) * 2;
                ldm4(fb, sb + G2_B + o);
            }
#pragma unroll
            for (int mf = 0; mf < 4; mf++)
#pragma unroll
                for (int nf = 0; nf < 2; nf++)
                    mma_f16(acc[mf][nf], ah[mf], fb + nf*2);
        }
        __syncthreads();
    }

#pragma unroll
    for (int mf = 0; mf < 4; mf++)
#pragma unroll
        for (int nf = 0; nf < 2; nf++) {
            int m = wm*64 + mf*16 + (lane >> 2);
            int d = d0 + wn*16 + nf*8 + (lane & 3)*2;
            float* c = acc[mf][nf];
#pragma unroll
            for (int half = 0; half < 2; half++) {
                int mr = m + half*8;
                int tok = toks_sh[mr];
                if (tok < 0) continue;
                float wt = wts_sh[mr];
                float* op = out + ((size_t)tok << 10) + d;
                atomicAdd(op,     wt * c[half*2]);
                atomicAdd(op + 1, wt * c[half*2+1]);
            }
        }
}

// ---------------- launch ----------------
extern "C" void kernel_launch(void* const* d_in, const int* in_sizes, int n_in,
                              void* d_out, int out_size) {
    const float* x    = (const float*)d_in[0];
    const float* rw   = (const float*)d_in[1];
    const float* bias = (const float*)d_in[2];
    const float* w1   = (const float*)d_in[3];
    const float* w2   = (const float*)d_in[4];
    const float* w3   = (const float*)d_in[5];
    const float* sw1  = (const float*)d_in[6];
    const float* sw2  = (const float*)d_in[7];
    const float* sw3  = (const float*)d_in[8];
    float* out = (float*)d_out;

    cudaFuncSetAttribute(gemm1_kernel, cudaFuncAttributeMaxDynamicSharedMemorySize, 2*G1_STG);
    cudaFuncSetAttribute(gemm2_kernel, cudaFuncAttributeMaxDynamicSharedMemorySize, 2*G2_STG);

    cudaMemsetAsync(out, 0, (size_t)out_size * sizeof(float));

    dim3 cb(32, 8);
    convert_weights<<<dim3(1024, 9, 3), cb>>>(w1, w2, w3, sw1, sw2, sw3);
    router_kernel<<<N_TOK/8, 256>>>(x, rw, bias);
    build_kernel<<<1, 256>>>();

    gemm1_kernel<<<dim3(MAX_TILES, HDIM/BN), 256, 2*G1_STG>>>();
    gemm2_kernel<<<dim3(MAX_TILES, DDIM/BN), 256, 2*G2_STG>>>(out);
}

// round 8
// speedup vs baseline: 3.3314x; 1.1148x over previous
#include <cuda_runtime.h>
#include <cuda_fp16.h>
#include <math.h>
#include <stdint.h>

#define N_TOK 1024
#define DDIM  1024
#define HDIM  1024
#define NEXP  8
#define TOPK  2
#define BM    128
#define BN    64
#define BK    64
#define MAX_ROWS  4096
#define MAX_TILES 32

// ---------------- device scratch ----------------
__device__ __half g_w1t[9ull*1024*1024];   // fp16 weights, transposed [slot][N][K]
__device__ __half g_w3t[9ull*1024*1024];
__device__ __half g_w2t[9ull*1024*1024];
__device__ __half g_xh[1024*1024];         // x hi/lo fp16 pair (22-bit x)
__device__ __half g_xl[1024*1024];
__device__ __half g_acth[(size_t)MAX_ROWS*HDIM];

__device__ int   g_sel[N_TOK*TOPK];
__device__ float g_wtk[N_TOK*TOPK];
__device__ int   g_cnt[NEXP];
__device__ int   g_tile_exp[MAX_TILES];
__device__ int   g_num_tiles;
__device__ int   g_row_tok[MAX_ROWS];
__device__ float g_row_wt[MAX_ROWS];

// ---------------- helpers ----------------
__device__ __forceinline__ uint32_t smem_u32(const void* p) {
    uint32_t a;
    asm("{ .reg .u64 t; cvta.to.shared.u64 t, %1; cvt.u32.u64 %0, t; }" : "=r"(a) : "l"(p));
    return a;
}
__device__ __forceinline__ void cp16(uint32_t dst, const void* src, int sz) {
    asm volatile("cp.async.cg.shared.global [%0], [%1], 16, %2;"
                 :: "r"(dst), "l"(src), "r"(sz) : "memory");
}
#define CP_COMMIT() asm volatile("cp.async.commit_group;" ::: "memory")
#define CP_WAIT(n)  asm volatile("cp.async.wait_group %0;" :: "n"(n) : "memory")

__device__ __forceinline__ void ldm4(uint32_t* r, uint32_t addr) {
    asm volatile("ldmatrix.sync.aligned.m8n8.x4.shared.b16 {%0,%1,%2,%3}, [%4];"
                 : "=r"(r[0]), "=r"(r[1]), "=r"(r[2]), "=r"(r[3]) : "r"(addr));
}
__device__ __forceinline__ void mma_f16(float* d, const uint32_t* a, const uint32_t* b) {
    asm volatile(
        "mma.sync.aligned.m16n8k16.row.col.f32.f16.f16.f32 "
        "{%0,%1,%2,%3},{%4,%5,%6,%7},{%8,%9},{%0,%1,%2,%3};"
        : "+f"(d[0]), "+f"(d[1]), "+f"(d[2]), "+f"(d[3])
        : "r"(a[0]), "r"(a[1]), "r"(a[2]), "r"(a[3]), "r"(b[0]), "r"(b[1]));
}
__device__ __forceinline__ uint32_t pack2h(float a, float b) {
    __half ha = __float2half_rn(a), hb = __float2half_rn(b);
    return (uint32_t)__half_as_ushort(ha) | ((uint32_t)__half_as_ushort(hb) << 16);
}
__device__ __forceinline__ uint32_t pack2hlo(float a, float b) {
    __half ha = __float2half_rn(a), hb = __float2half_rn(b);
    float ra = a - __half2float(ha), rb = b - __half2float(hb);
    return pack2h(ra, rb);
}

// ---------------- 1. convert+transpose weights -> fp16 [slot][N][K]; block0 inits ----------------
__global__ void convert_weights(const float* __restrict__ w1, const float* __restrict__ w2,
                                const float* __restrict__ w3,
                                const float* __restrict__ sw1, const float* __restrict__ sw2,
                                const float* __restrict__ sw3) {
    __shared__ float t[32][33];
    int e = blockIdx.y;                 // 0..8 (8 = shared)
    int mat = blockIdx.z;               // 0=w1, 1=w3, 2=w2
    int tile_r = (blockIdx.x >> 5) << 5;
    int tile_c = (blockIdx.x & 31) << 5;
    const float* src;
    __half* dst;
    size_t eo = (size_t)e << 20;
    if (mat == 0)      { src = (e < 8) ? w1 + eo : sw1; dst = g_w1t + eo; }
    else if (mat == 1) { src = (e < 8) ? w3 + eo : sw3; dst = g_w3t + eo; }
    else               { src = (e < 8) ? w2 + eo : sw2; dst = g_w2t + eo; }

    int tx = threadIdx.x, ty = threadIdx.y;
    int tid = ty * 32 + tx;

    if (blockIdx.x == 0 && e == 0 && mat == 0) {
        if (tid < NEXP) g_cnt[tid] = 0;
        for (int i = tid; i < MAX_ROWS; i += 256) { g_row_tok[i] = -1; g_row_wt[i] = 0.f; }
    }

#pragma unroll
    for (int j = 0; j < 4; j++)
        t[ty + 8*j][tx] = src[(size_t)(tile_r + ty + 8*j) * 1024 + tile_c + tx];
    __syncthreads();
    int l = tx & 15, half = tx >> 4;
#pragma unroll
    for (int j = 0; j < 2; j++) {
        int cy = ty + 8*(2*j + half);
        float v0 = t[2*l][cy], v1 = t[2*l+1][cy];
        uint32_t* d = (uint32_t*)(dst + (size_t)(tile_c + cy) * 1024 + tile_r) + l;
        *d = pack2h(v0, v1);
    }
}

// ---------------- 2. router + convert x + count ----------------
__global__ void router_kernel(const float* __restrict__ x,
                              const float* __restrict__ rw,
                              const float* __restrict__ bias) {
    int warp = threadIdx.x >> 5, lane = threadIdx.x & 31;
    int tok = blockIdx.x * 8 + warp;
    if (tok >= N_TOK) return;
    const float* xr = x + (size_t)tok * DDIM;

    float acc[NEXP];
#pragma unroll
    for (int e = 0; e < NEXP; e++) acc[e] = 0.f;
#pragma unroll
    for (int i = 0; i < 8; i++) {
        int d4 = lane + i * 32;
        float4 v = ((const float4*)xr)[d4];
        uint2 h  = make_uint2(pack2h(v.x, v.y), pack2h(v.z, v.w));
        uint2 lo = make_uint2(pack2hlo(v.x, v.y), pack2hlo(v.z, v.w));
        *(uint2*)(g_xh + (size_t)tok * DDIM + d4 * 4) = h;
        *(uint2*)(g_xl + (size_t)tok * DDIM + d4 * 4) = lo;
        int d = d4 * 4;
        const float* r0 = rw + (size_t)d * NEXP;
#pragma unroll
        for (int e = 0; e < NEXP; e++)
            acc[e] += v.x * r0[e] + v.y * r0[NEXP + e] + v.z * r0[2*NEXP + e] + v.w * r0[3*NEXP + e];
    }
#pragma unroll
    for (int e = 0; e < NEXP; e++)
#pragma unroll
        for (int o = 16; o > 0; o >>= 1)
            acc[e] += __shfl_xor_sync(0xffffffffu, acc[e], o);
    if (lane == 0) {
        float m = acc[0];
#pragma unroll
        for (int e = 1; e < NEXP; e++) m = fmaxf(m, acc[e]);
        float sc[NEXP]; float s = 0.f;
#pragma unroll
        for (int e = 0; e < NEXP; e++) { sc[e] = expf(acc[e] - m); s += sc[e]; }
        float inv = 1.f / s;
#pragma unroll
        for (int e = 0; e < NEXP; e++) sc[e] *= inv;
        int i0 = 0; float b0 = sc[0] + bias[0];
#pragma unroll
        for (int e = 1; e < NEXP; e++) { float v = sc[e] + bias[e]; if (v > b0) { b0 = v; i0 = e; } }
        int i1 = -1; float b1 = -1e30f;
#pragma unroll
        for (int e = 0; e < NEXP; e++) {
            if (e == i0) continue;
            float v = sc[e] + bias[e]; if (v > b1) { b1 = v; i1 = e; }
        }
        g_sel[tok*2]   = i0;  g_sel[tok*2+1] = i1;
        g_wtk[tok*2]   = sc[i0]; g_wtk[tok*2+1] = sc[i1];
        atomicAdd(&g_cnt[i0], 1);
        atomicAdd(&g_cnt[i1], 1);
    }
}

// ---------------- 3. build: offsets + scatter ----------------
__global__ void build_kernel() {
    __shared__ int off[NEXP+2], fill[NEXP];
    int tid = threadIdx.x;
    if (tid < NEXP) fill[tid] = 0;
    if (tid == 0) {
        int o = 0;
        for (int e = 0; e < NEXP; e++) { off[e] = o; o += ((g_cnt[e] + BM - 1) / BM) * BM; }
        off[NEXP] = o;
        int total = o + N_TOK;
        off[NEXP+1] = total;
        int nt = total / BM;
        g_num_tiles = nt;
        for (int t = 0; t < nt; t++) {
            int row = t * BM;
            int e = 0;
            while (e < NEXP+1 && row >= off[e+1]) e++;
            g_tile_exp[t] = e;   // e==8 -> shared-expert slot
        }
    }
    __syncthreads();
    for (int i = tid; i < N_TOK*TOPK; i += 256) {
        int e = g_sel[i];
        int p = off[e] + atomicAdd(&fill[e], 1);
        g_row_tok[p] = i >> 1;
        g_row_wt[p]  = g_wtk[i];
    }
    for (int t = tid; t < N_TOK; t += 256) {
        int p = off[NEXP] + t;
        g_row_tok[p] = t;
        g_row_wt[p]  = 1.0f;
    }
}

// ---------------- GEMM smem layout constants ----------------
#define RS 72                       // elems per row (64 + 8 pad), 144 B stride
#define G1_AH  0
#define G1_AL  18432                // 128*72*2
#define G1_B1  36864
#define G1_B3  46080
#define G1_STG 55296
#define G2_A   0
#define G2_B   18432
#define G2_STG 27648

// ---------------- 4. GEMM1: act = silu(x@W1) * (x@W3) ----------------
__global__ void __launch_bounds__(256, 2) gemm1_kernel() {
    extern __shared__ __align__(16) char dyn[];
    __shared__ int toks_sh[BM];

    int tile = blockIdx.x;
    if (tile >= g_num_tiles) return;
    int e  = g_tile_exp[tile];
    int h0 = blockIdx.y * BN;
    int tid = threadIdx.x, lane = tid & 31, wid = tid >> 5;
    int wm = wid & 1, wn = wid >> 1;      // warp tile: 64(m) x 16(n)

    if (tid < BM) toks_sh[tid] = g_row_tok[tile * BM + tid];
    __syncthreads();

    const __half* b1 = g_w1t + ((size_t)e << 20);
    const __half* b3 = g_w3t + ((size_t)e << 20);
    uint32_t smem = smem_u32(dyn);

    int frow = tid >> 3;
    int fk = (tid & 7) * 8;

    // fill addresses recomputed per stage (saves ~15 persistent regs vs arrays)
#define G1_FILL(k0, sb) do { \
    _Pragma("unroll") \
    for (int it = 0; it < 4; it++) { \
        int row = frow + 32 * it; \
        int tok = toks_sh[row]; \
        uint32_t ad = (sb) + (uint32_t)(row * RS + fk) * 2; \
        size_t ax = ((size_t)(tok < 0 ? 0 : tok) << 10) + fk + (k0); \
        int sz = tok < 0 ? 0 : 16; \
        cp16(ad + G1_AH, g_xh + ax, sz); \
        cp16(ad + G1_AL, g_xl + ax, sz); \
    } \
    _Pragma("unroll") \
    for (int it = 0; it < 2; it++) { \
        int row = frow + 32 * it; \
        uint32_t bd = (sb) + (uint32_t)(row * RS + fk) * 2; \
        size_t bo = ((size_t)(h0 + row) << 10) + fk + (k0); \
        cp16(bd + G1_B1, b1 + bo, 16); \
        cp16(bd + G1_B3, b3 + bo, 16); \
    } \
} while (0)

    float acc1[4][2][4], acc3[4][2][4];
#pragma unroll
    for (int i = 0; i < 4; i++)
#pragma unroll
        for (int j = 0; j < 2; j++)
#pragma unroll
            for (int k = 0; k < 4; k++) { acc1[i][j][k] = 0.f; acc3[i][j][k] = 0.f; }

    int lr = lane & 15, lc8 = (lane >> 4) * 8;
    uint32_t bbase = (uint32_t)((wn*16 + ((lane >> 4) << 3) + (lane & 7)) * RS
                   + (((lane >> 3) & 1) * 8));

    G1_FILL(0, smem);
    CP_COMMIT();

    const int NST = DDIM / BK;   // 16
    for (int s = 0; s < NST; s++) {
        if (s + 1 < NST) {
            uint32_t sb = smem + ((s + 1) & 1) * G1_STG;
            G1_FILL((s + 1) * BK, sb);
            CP_COMMIT();
            CP_WAIT(1);
        } else {
            CP_WAIT(0);
        }
        __syncthreads();
        uint32_t sb = smem + (s & 1) * G1_STG;
#pragma unroll
        for (int ks = 0; ks < 4; ks++) {
            uint32_t f1[4], f3[4];
            {
                uint32_t o = (bbase + ks*16) * 2;
                ldm4(f1, sb + G1_B1 + o);
                ldm4(f3, sb + G1_B3 + o);
            }
#pragma unroll
            for (int mf = 0; mf < 4; mf++) {
                uint32_t ah[4], al[4];
                uint32_t o = (uint32_t)((wm*64 + mf*16 + lr)*RS + ks*16 + lc8) * 2;
                ldm4(ah, sb + G1_AH + o);
                ldm4(al, sb + G1_AL + o);
#pragma unroll
                for (int nf = 0; nf < 2; nf++) {
                    mma_f16(acc1[mf][nf], ah, f1 + nf*2);
                    mma_f16(acc1[mf][nf], al, f1 + nf*2);
                    mma_f16(acc3[mf][nf], ah, f3 + nf*2);
                    mma_f16(acc3[mf][nf], al, f3 + nf*2);
                }
            }
        }
        __syncthreads();
    }

    // epilogue: silu(d1)*d3 -> fp16 (single precision-term act)
#pragma unroll
    for (int mf = 0; mf < 4; mf++)
#pragma unroll
        for (int nf = 0; nf < 2; nf++) {
            int m = wm*64 + mf*16 + (lane >> 2);
            int h = h0 + wn*16 + nf*8 + (lane & 3)*2;
            float* c1 = acc1[mf][nf];
            float* c3 = acc3[mf][nf];
#pragma unroll
            for (int half = 0; half < 2; half++) {
                float v1a = c1[half*2], v1b = c1[half*2+1];
                float v3a = c3[half*2], v3b = c3[half*2+1];
                float a0 = (v1a / (1.f + expf(-v1a))) * v3a;
                float a1 = (v1b / (1.f + expf(-v1b))) * v3b;
                size_t row = (size_t)(tile*BM + m + half*8);
                *(uint32_t*)(g_acth + (row << 10) + h) = pack2h(a0, a1);
            }
        }
}

// ---------------- 5. GEMM2: out[tok] += wt * (act @ W2); 3-stage single-sync ----------------
__global__ void __launch_bounds__(256, 2) gemm2_kernel(float* __restrict__ out) {
    extern __shared__ __align__(16) char dyn[];
    __shared__ int   toks_sh[BM];
    __shared__ float wts_sh[BM];

    int tile = blockIdx.x;
    if (tile >= g_num_tiles) return;
    int e  = g_tile_exp[tile];
    int d0 = blockIdx.y * BN;
    int tid = threadIdx.x, lane = tid & 31, wid = tid >> 5;
    int wm = wid & 1, wn = wid >> 1;

    if (tid < BM) {
        toks_sh[tid] = g_row_tok[tile * BM + tid];
        wts_sh[tid]  = g_row_wt[tile * BM + tid];
    }
    __syncthreads();

    const __half* bw = g_w2t + ((size_t)e << 20);
    uint32_t smem = smem_u32(dyn);

    int frow = tid >> 3;
    int fk = (tid & 7) * 8;

#define G2_FILL(k0, sb) do { \
    _Pragma("unroll") \
    for (int it = 0; it < 4; it++) { \
        int row = frow + 32 * it; \
        uint32_t ad = (sb) + (uint32_t)(row * RS + fk) * 2; \
        size_t ax = (((size_t)(tile*BM + row)) << 10) + fk + (k0); \
        cp16(ad + G2_A, g_acth + ax, 16); \
    } \
    _Pragma("unroll") \
    for (int it = 0; it < 2; it++) { \
        int row = frow + 32 * it; \
        uint32_t bd = (sb) + (uint32_t)(row * RS + fk) * 2; \
        size_t bo = ((size_t)(d0 + row) << 10) + fk + (k0); \
        cp16(bd + G2_B, bw + bo, 16); \
    } \
} while (0)

    float acc[4][2][4];
#pragma unroll
    for (int i = 0; i < 4; i++)
#pragma unroll
        for (int j = 0; j < 2; j++)
#pragma unroll
            for (int k = 0; k < 4; k++) acc[i][j][k] = 0.f;

    int lr = lane & 15, lc8 = (lane >> 4) * 8;
    uint32_t bbase = (uint32_t)((wn*16 + ((lane >> 4) << 3) + (lane & 7)) * RS
                   + (((lane >> 3) & 1) * 8));

    G2_FILL(0, smem);
    CP_COMMIT();
    G2_FILL(BK, smem + G2_STG);
    CP_COMMIT();

    const int NST = HDIM / BK;   // 16
    int cur = 0, nxt2 = 2;       // rotating stage indices
    for (int s = 0; s < NST; s++) {
        CP_WAIT(1);
        __syncthreads();
        if (s + 2 < NST) {
            G2_FILL((s + 2) * BK, smem + nxt2 * G2_STG);
            CP_COMMIT();
        }
        uint32_t sb = smem + cur * G2_STG;
#pragma unroll
        for (int ks = 0; ks < 4; ks++) {
            uint32_t fb[4];
            {
                uint32_t o = (bbase + ks*16) * 2;
                ldm4(fb, sb + G2_B + o);
            }
#pragma unroll
            for (int mf = 0; mf < 4; mf++) {
                uint32_t ah[4];
                uint32_t o = (uint32_t)((wm*64 + mf*16 + lr)*RS + ks*16 + lc8) * 2;
                ldm4(ah, sb + G2_A + o);
#pragma unroll
                for (int nf = 0; nf < 2; nf++)
                    mma_f16(acc[mf][nf], ah, fb + nf*2);
            }
        }
        cur = (cur == 2) ? 0 : cur + 1;
        nxt2 = (nxt2 == 2) ? 0 : nxt2 + 1;
    }

#pragma unroll
    for (int mf = 0; mf < 4; mf++)
#pragma unroll
        for (int nf = 0; nf < 2; nf++) {
            int m = wm*64 + mf*16 + (lane >> 2);
            int d = d0 + wn*16 + nf*8 + (lane & 3)*2;
            float* c = acc[mf][nf];
#pragma unroll
            for (int half = 0; half < 2; half++) {
                int mr = m + half*8;
                int tok = toks_sh[mr];
                if (tok < 0) continue;
                float wt = wts_sh[mr];
                float* op = out + ((size_t)tok << 10) + d;
                atomicAdd(op,     wt * c[half*2]);
                atomicAdd(op + 1, wt * c[half*2+1]);
            }
        }
}

// ---------------- launch ----------------
extern "C" void kernel_launch(void* const* d_in, const int* in_sizes, int n_in,
                              void* d_out, int out_size) {
    const float* x    = (const float*)d_in[0];
    const float* rw   = (const float*)d_in[1];
    const float* bias = (const float*)d_in[2];
    const float* w1   = (const float*)d_in[3];
    const float* w2   = (const float*)d_in[4];
    const float* w3   = (const float*)d_in[5];
    const float* sw1  = (const float*)d_in[6];
    const float* sw2  = (const float*)d_in[7];
    const float* sw3  = (const float*)d_in[8];
    float* out = (float*)d_out;

    cudaFuncSetAttribute(gemm1_kernel, cudaFuncAttributeMaxDynamicSharedMemorySize, 2*G1_STG);
    cudaFuncSetAttribute(gemm2_kernel, cudaFuncAttributeMaxDynamicSharedMemorySize, 3*G2_STG);

    cudaMemsetAsync(out, 0, (size_t)out_size * sizeof(float));

    dim3 cb(32, 8);
    convert_weights<<<dim3(1024, 9, 3), cb>>>(w1, w2, w3, sw1, sw2, sw3);
    router_kernel<<<N_TOK/8, 256>>>(x, rw, bias);
    build_kernel<<<1, 256>>>();

    gemm1_kernel<<<dim3(MAX_TILES, HDIM/BN), 256, 2*G1_STG>>>();
    gemm2_kernel<<<dim3(MAX_TILES, DDIM/BN), 256, 3*G2_STG>>>(out);
}

// round 10
// speedup vs baseline: 3.7207x; 1.1169x over previous
#include <cuda_runtime.h>
#include <cuda_fp16.h>
#include <math.h>
#include <stdint.h>

#define N_TOK 1024
#define DDIM  1024
#define HDIM  1024
#define NEXP  8
#define TOPK  2
#define BM    128
#define BN    64
#define BK    64
#define MAX_ROWS  4096
#define MAX_TILES 32

// ---------------- device scratch ----------------
__device__ __half g_w1t[9ull*1024*1024];   // fp16 weights, transposed [slot][N][K]
__device__ __half g_w3t[9ull*1024*1024];
__device__ __half g_w2t[9ull*1024*1024];
__device__ __half g_xh[1024*1024];         // x fp16
__device__ __half g_acth[(size_t)MAX_ROWS*HDIM];

__device__ int   g_sel[N_TOK*TOPK];
__device__ float g_wtk[N_TOK*TOPK];
__device__ int   g_cnt[NEXP];
__device__ int   g_tile_exp[MAX_TILES];
__device__ int   g_num_tiles;
__device__ int   g_row_tok[MAX_ROWS];
__device__ float g_row_wt[MAX_ROWS];

// ---------------- helpers ----------------
__device__ __forceinline__ uint32_t smem_u32(const void* p) {
    uint32_t a;
    asm("{ .reg .u64 t; cvta.to.shared.u64 t, %1; cvt.u32.u64 %0, t; }" : "=r"(a) : "l"(p));
    return a;
}
__device__ __forceinline__ void cp16(uint32_t dst, const void* src, int sz) {
    asm volatile("cp.async.cg.shared.global [%0], [%1], 16, %2;"
                 :: "r"(dst), "l"(src), "r"(sz) : "memory");
}
#define CP_COMMIT() asm volatile("cp.async.commit_group;" ::: "memory")
#define CP_WAIT(n)  asm volatile("cp.async.wait_group %0;" :: "n"(n) : "memory")

__device__ __forceinline__ void ldm4(uint32_t* r, uint32_t addr) {
    asm volatile("ldmatrix.sync.aligned.m8n8.x4.shared.b16 {%0,%1,%2,%3}, [%4];"
                 : "=r"(r[0]), "=r"(r[1]), "=r"(r[2]), "=r"(r[3]) : "r"(addr));
}
__device__ __forceinline__ void mma_f16(float* d, const uint32_t* a, const uint32_t* b) {
    asm volatile(
        "mma.sync.aligned.m16n8k16.row.col.f32.f16.f16.f32 "
        "{%0,%1,%2,%3},{%4,%5,%6,%7},{%8,%9},{%0,%1,%2,%3};"
        : "+f"(d[0]), "+f"(d[1]), "+f"(d[2]), "+f"(d[3])
        : "r"(a[0]), "r"(a[1]), "r"(a[2]), "r"(a[3]), "r"(b[0]), "r"(b[1]));
}
__device__ __forceinline__ uint32_t pack2h(float a, float b) {
    __half ha = __float2half_rn(a), hb = __float2half_rn(b);
    return (uint32_t)__half_as_ushort(ha) | ((uint32_t)__half_as_ushort(hb) << 16);
}

// ---------------- 1. convert+transpose weights -> fp16 [slot][N][K]; block0 inits ----------------
__global__ void convert_weights(const float* __restrict__ w1, const float* __restrict__ w2,
                                const float* __restrict__ w3,
                                const float* __restrict__ sw1, const float* __restrict__ sw2,
                                const float* __restrict__ sw3) {
    __shared__ float t[32][33];
    int e = blockIdx.y;                 // 0..8 (8 = shared)
    int mat = blockIdx.z;               // 0=w1, 1=w3, 2=w2
    int tile_r = (blockIdx.x >> 5) << 5;
    int tile_c = (blockIdx.x & 31) << 5;
    const float* src;
    __half* dst;
    size_t eo = (size_t)e << 20;
    if (mat == 0)      { src = (e < 8) ? w1 + eo : sw1; dst = g_w1t + eo; }
    else if (mat == 1) { src = (e < 8) ? w3 + eo : sw3; dst = g_w3t + eo; }
    else               { src = (e < 8) ? w2 + eo : sw2; dst = g_w2t + eo; }

    int tx = threadIdx.x, ty = threadIdx.y;
    int tid = ty * 32 + tx;

    if (blockIdx.x == 0 && e == 0 && mat == 0) {
        if (tid < NEXP) g_cnt[tid] = 0;
        for (int i = tid; i < MAX_ROWS; i += 256) { g_row_tok[i] = -1; g_row_wt[i] = 0.f; }
    }

#pragma unroll
    for (int j = 0; j < 4; j++)
        t[ty + 8*j][tx] = src[(size_t)(tile_r + ty + 8*j) * 1024 + tile_c + tx];
    __syncthreads();
    int l = tx & 15, half = tx >> 4;
#pragma unroll
    for (int j = 0; j < 2; j++) {
        int cy = ty + 8*(2*j + half);
        float v0 = t[2*l][cy], v1 = t[2*l+1][cy];
        uint32_t* d = (uint32_t*)(dst + (size_t)(tile_c + cy) * 1024 + tile_r) + l;
        *d = pack2h(v0, v1);
    }
}

// ---------------- 2. router + convert x + count ----------------
__global__ void router_kernel(const float* __restrict__ x,
                              const float* __restrict__ rw,
                              const float* __restrict__ bias) {
    int warp = threadIdx.x >> 5, lane = threadIdx.x & 31;
    int tok = blockIdx.x * 8 + warp;
    if (tok >= N_TOK) return;
    const float* xr = x + (size_t)tok * DDIM;

    float acc[NEXP];
#pragma unroll
    for (int e = 0; e < NEXP; e++) acc[e] = 0.f;
#pragma unroll
    for (int i = 0; i < 8; i++) {
        int d4 = lane + i * 32;
        float4 v = ((const float4*)xr)[d4];
        uint2 h = make_uint2(pack2h(v.x, v.y), pack2h(v.z, v.w));
        *(uint2*)(g_xh + (size_t)tok * DDIM + d4 * 4) = h;
        int d = d4 * 4;
        const float* r0 = rw + (size_t)d * NEXP;
#pragma unroll
        for (int e = 0; e < NEXP; e++)
            acc[e] += v.x * r0[e] + v.y * r0[NEXP + e] + v.z * r0[2*NEXP + e] + v.w * r0[3*NEXP + e];
    }
#pragma unroll
    for (int e = 0; e < NEXP; e++)
#pragma unroll
        for (int o = 16; o > 0; o >>= 1)
            acc[e] += __shfl_xor_sync(0xffffffffu, acc[e], o);
    if (lane == 0) {
        float m = acc[0];
#pragma unroll
        for (int e = 1; e < NEXP; e++) m = fmaxf(m, acc[e]);
        float sc[NEXP]; float s = 0.f;
#pragma unroll
        for (int e = 0; e < NEXP; e++) { sc[e] = expf(acc[e] - m); s += sc[e]; }
        float inv = 1.f / s;
#pragma unroll
        for (int e = 0; e < NEXP; e++) sc[e] *= inv;
        int i0 = 0; float b0 = sc[0] + bias[0];
#pragma unroll
        for (int e = 1; e < NEXP; e++) { float v = sc[e] + bias[e]; if (v > b0) { b0 = v; i0 = e; } }
        int i1 = -1; float b1 = -1e30f;
#pragma unroll
        for (int e = 0; e < NEXP; e++) {
            if (e == i0) continue;
            float v = sc[e] + bias[e]; if (v > b1) { b1 = v; i1 = e; }
        }
        g_sel[tok*2]   = i0;  g_sel[tok*2+1] = i1;
        g_wtk[tok*2]   = sc[i0]; g_wtk[tok*2+1] = sc[i1];
        atomicAdd(&g_cnt[i0], 1);
        atomicAdd(&g_cnt[i1], 1);
    }
}

// ---------------- 3. build: offsets + scatter ----------------
__global__ void build_kernel() {
    __shared__ int off[NEXP+2], fill[NEXP];
    int tid = threadIdx.x;
    if (tid < NEXP) fill[tid] = 0;
    if (tid == 0) {
        int o = 0;
        for (int e = 0; e < NEXP; e++) { off[e] = o; o += ((g_cnt[e] + BM - 1) / BM) * BM; }
        off[NEXP] = o;
        int total = o + N_TOK;
        off[NEXP+1] = total;
        int nt = total / BM;
        g_num_tiles = nt;
        for (int t = 0; t < nt; t++) {
            int row = t * BM;
            int e = 0;
            while (e < NEXP+1 && row >= off[e+1]) e++;
            g_tile_exp[t] = e;   // e==8 -> shared-expert slot
        }
    }
    __syncthreads();
    for (int i = tid; i < N_TOK*TOPK; i += 256) {
        int e = g_sel[i];
        int p = off[e] + atomicAdd(&fill[e], 1);
        g_row_tok[p] = i >> 1;
        g_row_wt[p]  = g_wtk[i];
    }
    for (int t = tid; t < N_TOK; t += 256) {
        int p = off[NEXP] + t;
        g_row_tok[p] = t;
        g_row_wt[p]  = 1.0f;
    }
}

// ---------------- GEMM smem layout constants ----------------
#define RS 72                       // elems per row (64 + 8 pad), 144 B stride
#define G1_A   0
#define G1_B1  18432                // 128*72*2
#define G1_B3  27648
#define G1_STG 36864
#define G2_A   0
#define G2_B   18432
#define G2_STG 27648

// ---------------- 4. GEMM1: act = silu(x@W1) * (x@W3); 3-stage single-sync ----------------
__global__ void __launch_bounds__(256, 2) gemm1_kernel() {
    extern __shared__ __align__(16) char dyn[];
    __shared__ int toks_sh[BM];

    int tile = blockIdx.x;
    if (tile >= g_num_tiles) return;
    int e  = g_tile_exp[tile];
    int h0 = blockIdx.y * BN;
    int tid = threadIdx.x, lane = tid & 31, wid = tid >> 5;
    int wm = wid & 1, wn = wid >> 1;      // warp tile: 64(m) x 16(n)

    if (tid < BM) toks_sh[tid] = g_row_tok[tile * BM + tid];
    __syncthreads();

    const __half* b1 = g_w1t + ((size_t)e << 20);
    const __half* b3 = g_w3t + ((size_t)e << 20);
    uint32_t smem = smem_u32(dyn);

    int frow = tid >> 3;
    int fk = (tid & 7) * 8;

#define G1_FILL(k0, sb) do { \
    _Pragma("unroll") \
    for (int it = 0; it < 4; it++) { \
        int row = frow + 32 * it; \
        int tok = toks_sh[row]; \
        uint32_t ad = (sb) + G1_A + (uint32_t)(row * RS + fk) * 2; \
        size_t ax = ((size_t)(tok < 0 ? 0 : tok) << 10) + fk + (k0); \
        cp16(ad, g_xh + ax, tok < 0 ? 0 : 16); \
    } \
    _Pragma("unroll") \
    for (int it = 0; it < 2; it++) { \
        int row = frow + 32 * it; \
        uint32_t bd = (sb) + (uint32_t)(row * RS + fk) * 2; \
        size_t bo = ((size_t)(h0 + row) << 10) + fk + (k0); \
        cp16(bd + G1_B1, b1 + bo, 16); \
        cp16(bd + G1_B3, b3 + bo, 16); \
    } \
} while (0)

    float acc1[4][2][4], acc3[4][2][4];
#pragma unroll
    for (int i = 0; i < 4; i++)
#pragma unroll
        for (int j = 0; j < 2; j++)
#pragma unroll
            for (int k = 0; k < 4; k++) { acc1[i][j][k] = 0.f; acc3[i][j][k] = 0.f; }

    int lr = lane & 15, lc8 = (lane >> 4) * 8;
    uint32_t bbase = (uint32_t)((wn*16 + ((lane >> 4) << 3) + (lane & 7)) * RS
                   + (((lane >> 3) & 1) * 8));

    G1_FILL(0, smem);
    CP_COMMIT();
    G1_FILL(BK, smem + G1_STG);
    CP_COMMIT();

    const int NST = DDIM / BK;   // 16
    int cur = 0, nxt2 = 2;
    for (int s = 0; s < NST; s++) {
        CP_WAIT(1);
        __syncthreads();
        if (s + 2 < NST) {
            G1_FILL((s + 2) * BK, smem + nxt2 * G1_STG);
            CP_COMMIT();
        }
        uint32_t sb = smem + cur * G1_STG;
#pragma unroll
        for (int ks = 0; ks < 4; ks++) {
            uint32_t f1[4], f3[4];
            {
                uint32_t o = (bbase + ks*16) * 2;
                ldm4(f1, sb + G1_B1 + o);
                ldm4(f3, sb + G1_B3 + o);
            }
#pragma unroll
            for (int mf = 0; mf < 4; mf++) {
                uint32_t ah[4];
                uint32_t o = (uint32_t)((wm*64 + mf*16 + lr)*RS + ks*16 + lc8) * 2;
                ldm4(ah, sb + G1_A + o);
#pragma unroll
                for (int nf = 0; nf < 2; nf++) {
                    mma_f16(acc1[mf][nf], ah, f1 + nf*2);
                    mma_f16(acc3[mf][nf], ah, f3 + nf*2);
                }
            }
        }
        cur = (cur == 2) ? 0 : cur + 1;
        nxt2 = (nxt2 == 2) ? 0 : nxt2 + 1;
    }

    // epilogue: silu(d1)*d3 -> fp16 act
#pragma unroll
    for (int mf = 0; mf < 4; mf++)
#pragma unroll
        for (int nf = 0; nf < 2; nf++) {
            int m = wm*64 + mf*16 + (lane >> 2);
            int h = h0 + wn*16 + nf*8 + (lane & 3)*2;
            float* c1 = acc1[mf][nf];
            float* c3 = acc3[mf][nf];
#pragma unroll
            for (int half = 0; half < 2; half++) {
                float v1a = c1[half*2], v1b = c1[half*2+1];
                float v3a = c3[half*2], v3b = c3[half*2+1];
                float a0 = (v1a / (1.f + expf(-v1a))) * v3a;
                float a1 = (v1b / (1.f + expf(-v1b))) * v3b;
                size_t row = (size_t)(tile*BM + m + half*8);
                *(uint32_t*)(g_acth + (row << 10) + h) = pack2h(a0, a1);
            }
        }
}

// ---------------- 5. GEMM2: out[tok] += wt * (act @ W2); 3-stage single-sync ----------------
__global__ void __launch_bounds__(256, 2) gemm2_kernel(float* __restrict__ out) {
    extern __shared__ __align__(16) char dyn[];
    __shared__ int   toks_sh[BM];
    __shared__ float wts_sh[BM];

    int tile = blockIdx.x;
    if (tile >= g_num_tiles) return;
    int e  = g_tile_exp[tile];
    int d0 = blockIdx.y * BN;
    int tid = threadIdx.x, lane = tid & 31, wid = tid >> 5;
    int wm = wid & 1, wn = wid >> 1;

    if (tid < BM) {
        toks_sh[tid] = g_row_tok[tile * BM + tid];
        wts_sh[tid]  = g_row_wt[tile * BM + tid];
    }
    __syncthreads();

    const __half* bw = g_w2t + ((size_t)e << 20);
    uint32_t smem = smem_u32(dyn);

    int frow = tid >> 3;
    int fk = (tid & 7) * 8;

#define G2_FILL(k0, sb) do { \
    _Pragma("unroll") \
    for (int it = 0; it < 4; it++) { \
        int row = frow + 32 * it; \
        uint32_t ad = (sb) + (uint32_t)(row * RS + fk) * 2; \
        size_t ax = (((size_t)(tile*BM + row)) << 10) + fk + (k0); \
        cp16(ad + G2_A, g_acth + ax, 16); \
    } \
    _Pragma("unroll") \
    for (int it = 0; it < 2; it++) { \
        int row = frow + 32 * it; \
        uint32_t bd = (sb) + (uint32_t)(row * RS + fk) * 2; \
        size_t bo = ((size_t)(d0 + row) << 10) + fk + (k0); \
        cp16(bd + G2_B, bw + bo, 16); \
    } \
} while (0)

    float acc[4][2][4];
#pragma unroll
    for (int i = 0; i < 4; i++)
#pragma unroll
        for (int j = 0; j < 2; j++)
#pragma unroll
            for (int k = 0; k < 4; k++) acc[i][j][k] = 0.f;

    int lr = lane & 15, lc8 = (lane >> 4) * 8;
    uint32_t bbase = (uint32_t)((wn*16 + ((lane >> 4) << 3) + (lane & 7)) * RS
                   + (((lane >> 3) & 1) * 8));

    G2_FILL(0, smem);
    CP_COMMIT();
    G2_FILL(BK, smem + G2_STG);
    CP_COMMIT();

    const int NST = HDIM / BK;   // 16
    int cur = 0, nxt2 = 2;
    for (int s = 0; s < NST; s++) {
        CP_WAIT(1);
        __syncthreads();
        if (s + 2 < NST) {
            G2_FILL((s + 2) * BK, smem + nxt2 * G2_STG);
            CP_COMMIT();
        }
        uint32_t sb = smem + cur * G2_STG;
#pragma unroll
        for (int ks = 0; ks < 4; ks++) {
            uint32_t fb[4];
            {
                uint32_t o = (bbase + ks*16) * 2;
                ldm4(fb, sb + G2_B + o);
            }
#pragma unroll
            for (int mf = 0; mf < 4; mf++) {
                uint32_t ah[4];
                uint32_t o = (uint32_t)((wm*64 + mf*16 + lr)*RS + ks*16 + lc8) * 2;
                ldm4(ah, sb + G2_A + o);
#pragma unroll
                for (int nf = 0; nf < 2; nf++)
                    mma_f16(acc[mf][nf], ah, fb + nf*2);
            }
        }
        cur = (cur == 2) ? 0 : cur + 1;
        nxt2 = (nxt2 == 2) ? 0 : nxt2 + 1;
    }

#pragma unroll
    for (int mf = 0; mf < 4; mf++)
#pragma unroll
        for (int nf = 0; nf < 2; nf++) {
            int m = wm*64 + mf*16 + (lane >> 2);
            int d = d0 + wn*16 + nf*8 + (lane & 3)*2;
            float* c = acc[mf][nf];
#pragma unroll
            for (int half = 0; half < 2; half++) {
                int mr = m + half*8;
                int tok = toks_sh[mr];
                if (tok < 0) continue;
                float wt = wts_sh[mr];
                float* op = out + ((size_t)tok << 10) + d;
                atomicAdd(op,     wt * c[half*2]);
                atomicAdd(op + 1, wt * c[half*2+1]);
            }
        }
}

// ---------------- launch ----------------
extern "C" void kernel_launch(void* const* d_in, const int* in_sizes, int n_in,
                              void* d_out, int out_size) {
    const float* x    = (const float*)d_in[0];
    const float* rw   = (const float*)d_in[1];
    const float* bias = (const float*)d_in[2];
    const float* w1   = (const float*)d_in[3];
    const float* w2   = (const float*)d_in[4];
    const float* w3   = (const float*)d_in[5];
    const float* sw1  = (const float*)d_in[6];
    const float* sw2  = (const float*)d_in[7];
    const float* sw3  = (const float*)d_in[8];
    float* out = (float*)d_out;

    cudaFuncSetAttribute(gemm1_kernel, cudaFuncAttributeMaxDynamicSharedMemorySize, 3*G1_STG);
    cudaFuncSetAttribute(gemm2_kernel, cudaFuncAttributeMaxDynamicSharedMemorySize, 3*G2_STG);

    cudaMemsetAsync(out, 0, (size_t)out_size * sizeof(float));

    dim3 cb(32, 8);
    convert_weights<<<dim3(1024, 9, 3), cb>>>(w1, w2, w3, sw1, sw2, sw3);
    router_kernel<<<N_TOK/8, 256>>>(x, rw, bias);
    build_kernel<<<1, 256>>>();

    gemm1_kernel<<<dim3(MAX_TILES, HDIM/BN), 256, 3*G1_STG>>>();
    gemm2_kernel<<<dim3(MAX_TILES, DDIM/BN), 256, 3*G2_STG>>>(out);
}